// round 7
// baseline (speedup 1.0000x reference)
#include <cuda_runtime.h>
#include <math.h>
#include <stdint.h>

#define IMGS   457
#define HPAD   464
#define HP     29
#define NTOK   841
#define BATCH  8
#define DIM    256
#define MTOK   (BATCH*NTOK)   // 6728
#define NHEADS 8
#define DH     32

// ---------------- scratch (device globals; no allocations) ----------------
__device__ float g_tok [MTOK*1280];
__device__ float g_t   [MTOK*DIM];
__device__ float g_ln  [MTOK*DIM];
__device__ float g_qkv [MTOK*768];
__device__ float g_attn[MTOK*DIM];
__device__ float g_ff  [MTOK*1024];

// pre-truncated (tf32) weights
#define W_SPT_OFF  0
#define W_SPT_SZ   (256*1280)
#define W_QKV_OFF  (W_SPT_OFF+W_SPT_SZ)
#define W_QKV_SZ   (3*768*256)
#define W_WOUT_OFF (W_QKV_OFF+W_QKV_SZ)
#define W_WOUT_SZ  (3*256*256)
#define W_FF1_OFF  (W_WOUT_OFF+W_WOUT_SZ)
#define W_FF1_SZ   (3*1024*256)
#define W_FF2_OFF  (W_FF1_OFF+W_FF1_SZ)
#define W_FF2_SZ   (3*256*1024)
#define W_PIX_OFF  (W_FF2_OFF+W_FF2_SZ)
#define W_PIX_SZ   (256*256)
#define W_TOTAL    (W_PIX_OFF+W_PIX_SZ)
__device__ float g_wtf[W_TOTAL];

__device__ __forceinline__ uint32_t f2tf(float f) {
    uint32_t r;
    asm("cvt.rna.tf32.f32 %0, %1;" : "=r"(r) : "f"(f));
    return r;
}
__device__ __forceinline__ float ftrunc_tf(float f) { return __uint_as_float(f2tf(f)); }

__global__ void convert_w(const float* __restrict__ spt, const float* __restrict__ qkv,
                          const float* __restrict__ wo, const float* __restrict__ f1,
                          const float* __restrict__ f2w, const float* __restrict__ px) {
    int i4 = blockIdx.x * 256 + threadIdx.x;
    if (i4 >= W_TOTAL / 4) return;
    int i = i4 * 4;
    const float* src; int off;
    if      (i < W_QKV_OFF)  { src = spt; off = 0; }
    else if (i < W_WOUT_OFF) { src = qkv; off = W_QKV_OFF; }
    else if (i < W_FF1_OFF)  { src = wo;  off = W_WOUT_OFF; }
    else if (i < W_FF2_OFF)  { src = f1;  off = W_FF1_OFF; }
    else if (i < W_PIX_OFF)  { src = f2w; off = W_FF2_OFF; }
    else                     { src = px;  off = W_PIX_OFF; }
    float4 v = *(const float4*)(src + (i - off));
    v.x = ftrunc_tf(v.x); v.y = ftrunc_tf(v.y);
    v.z = ftrunc_tf(v.z); v.w = ftrunc_tf(v.w);
    *(float4*)&g_wtf[i] = v;
}

// ---------------- tokenize: pad + 5 shifted rolls + patchify --------------
__global__ void tokenize_kernel(const float* __restrict__ x) {
    int idx = blockIdx.x * blockDim.x + threadIdx.x;
    const int total = MTOK * 1280;
    if (idx >= total) return;
    int c = idx % 1280;
    int m = idx / 1280;
    int b = m / NTOK;
    int n = m % NTOK;
    int py = n / HP, px = n % HP;
    int s  = c / 256;
    int pr = (c % 256) / 16;
    int pc = c % 16;
    const int dxs[5] = {0, -8, 8, -8, 8};
    const int dys[5] = {0, -8, -8, 8, 8};
    int y  = py * 16 + pr - dys[s];
    int xx = px * 16 + pc - dxs[s];
    y  = (y  + HPAD) % HPAD;
    xx = (xx + HPAD) % HPAD;
    float v = 0.f;
    if (y < IMGS && xx < IMGS)
        v = x[((size_t)b * IMGS + y) * IMGS + xx];
    g_tok[idx] = ftrunc_tf(v);
}

// ---------------- tf32 tensor-core GEMM: 64x64 warp tiles ------------------
// BM=128, BN=128, BK=32; 128 threads (4 warps, 2x2), warp tile 64x64.
// 2-stage cp.async pipeline, 64 KB dynamic smem, XOR-swizzled.
__device__ __forceinline__ void mma_tf32(float c[4], const uint32_t a[4],
                                         uint32_t b0, uint32_t b1) {
    asm volatile(
        "mma.sync.aligned.m16n8k8.row.col.f32.tf32.tf32.f32 "
        "{%0,%1,%2,%3}, {%4,%5,%6,%7}, {%8,%9}, {%0,%1,%2,%3};"
        : "+f"(c[0]), "+f"(c[1]), "+f"(c[2]), "+f"(c[3])
        : "r"(a[0]), "r"(a[1]), "r"(a[2]), "r"(a[3]), "r"(b0), "r"(b1));
}
__device__ __forceinline__ float gelu_exact(float v) {
    return 0.5f * v * (1.0f + erff(v * 0.70710678118654752440f));
}
__device__ __forceinline__ void cp16(uint32_t saddr, const float* g, bool pred) {
    asm volatile("cp.async.cg.shared.global [%0], [%1], 16, %2;"
                 :: "r"(saddr), "l"(g), "r"(pred ? 16 : 0));
}
__device__ __forceinline__ void cp_commit() { asm volatile("cp.async.commit_group;"); }
template<int N>
__device__ __forceinline__ void cp_wait() {
    asm volatile("cp.async.wait_group %0;" :: "n"(N));
}
__device__ __forceinline__ int swz(int row, int col) {
    return row * 32 + (col ^ ((row & 7) * 4));
}

#define GEMM_SMEM (4 * 4096 * 4)   // 2 stages x (A 128x32 + W 128x32) floats

template<int ACT, bool HASBIAS, bool HASRES, bool POSMOD, bool TRUNC>
__global__ void __launch_bounds__(128, 2)
gemm_tc(const float* __restrict__ A, const float* __restrict__ W,
        const float* __restrict__ bias, const float* __restrict__ res,
        float* __restrict__ C, int M, int Nn, int K) {
    extern __shared__ float smem[];
    float* As = smem;               // [2][128*32]
    float* Ws = smem + 2 * 4096;    // [2][128*32]
    const int tid  = threadIdx.x;
    const int wid  = tid >> 5, lane = tid & 31;
    const int wm   = wid & 1,  wn   = wid >> 1;
    const int gid  = lane >> 2, tig = lane & 3;
    const int m0   = blockIdx.y * 128, n0 = blockIdx.x * 128;

    const int lrow = tid >> 3;          // 0..15
    const int lc4  = (tid & 7) * 4;

    uint32_t As_base = (uint32_t)__cvta_generic_to_shared(As);
    uint32_t Ws_base = (uint32_t)__cvta_generic_to_shared(Ws);

    float acc[4][8][4] = {};
    const int ktiles = K >> 5;

    auto load_tile = [&](int kt, int buf) {
        const float* Ag = A + (size_t)m0 * K + kt * 32;
        #pragma unroll
        for (int i = 0; i < 8; i++) {
            int row = lrow + i * 16;
            uint32_t s = As_base + (buf * 4096 + swz(row, lc4)) * 4;
            cp16(s, Ag + (size_t)row * K + lc4, (m0 + row) < M);
        }
        const float* Wg = W + (size_t)n0 * K + kt * 32;
        #pragma unroll
        for (int i = 0; i < 8; i++) {
            int row = lrow + i * 16;
            uint32_t s = Ws_base + (buf * 4096 + swz(row, lc4)) * 4;
            cp16(s, Wg + (size_t)row * K + lc4, true);
        }
    };

    load_tile(0, 0);
    cp_commit();

    for (int kt = 0; kt < ktiles; kt++) {
        if (kt + 1 < ktiles) { load_tile(kt + 1, (kt + 1) & 1); cp_commit(); cp_wait<1>(); }
        else                 { cp_wait<0>(); }
        __syncthreads();

        const float* as = As + (kt & 1) * 4096;
        const float* ws = Ws + (kt & 1) * 4096;
        #pragma unroll
        for (int ks = 0; ks < 32; ks += 8) {
            uint32_t af[4][4];
            #pragma unroll
            for (int mt = 0; mt < 4; mt++) {
                int r0 = wm * 64 + mt * 16 + gid;
                af[mt][0] = __float_as_uint(as[swz(r0,     ks + tig)]);
                af[mt][1] = __float_as_uint(as[swz(r0 + 8, ks + tig)]);
                af[mt][2] = __float_as_uint(as[swz(r0,     ks + tig + 4)]);
                af[mt][3] = __float_as_uint(as[swz(r0 + 8, ks + tig + 4)]);
            }
            #pragma unroll
            for (int nt = 0; nt < 8; nt++) {
                int nr = wn * 64 + nt * 8 + gid;
                uint32_t b0 = __float_as_uint(ws[swz(nr, ks + tig)]);
                uint32_t b1 = __float_as_uint(ws[swz(nr, ks + tig + 4)]);
                #pragma unroll
                for (int mt = 0; mt < 4; mt++)
                    mma_tf32(acc[mt][nt], af[mt], b0, b1);
            }
        }
        __syncthreads();
    }

    #pragma unroll
    for (int mt = 0; mt < 4; mt++) {
        #pragma unroll
        for (int half = 0; half < 2; half++) {
            int m = m0 + wm * 64 + mt * 16 + gid + half * 8;
            if (m >= M) continue;
            int mres = POSMOD ? (m % NTOK) : m;
            #pragma unroll
            for (int nt = 0; nt < 8; nt++) {
                int n = n0 + wn * 64 + nt * 8 + tig * 2;
                float v0 = acc[mt][nt][half * 2 + 0];
                float v1 = acc[mt][nt][half * 2 + 1];
                if (HASBIAS) { v0 += bias[n]; v1 += bias[n + 1]; }
                if (ACT == 1) { v0 = gelu_exact(v0); v1 = gelu_exact(v1); }
                if (HASRES) {
                    float2 r = *(const float2*)&res[(size_t)mres * Nn + n];
                    v0 += r.x; v1 += r.y;
                }
                if (TRUNC) { v0 = ftrunc_tf(v0); v1 = ftrunc_tf(v1); }
                *(float2*)&C[(size_t)m * Nn + n] = make_float2(v0, v1);
            }
        }
    }
}

// ---------------- LayerNorm (warp per token, dim=256, tf32-truncated out) --
__global__ void ln_kernel(const float* __restrict__ in, const float* __restrict__ w,
                          const float* __restrict__ b, float* __restrict__ out) {
    int warp = threadIdx.x / 32, lane = threadIdx.x % 32;
    int m = blockIdx.x * 8 + warp;
    if (m >= MTOK) return;
    const float* row = in + (size_t)m * DIM;
    float vals[8], s = 0.f, s2 = 0.f;
    #pragma unroll
    for (int k = 0; k < 8; k++) {
        float v = row[lane + 32 * k];
        vals[k] = v; s += v; s2 += v * v;
    }
    #pragma unroll
    for (int o = 16; o; o >>= 1) {
        s  += __shfl_xor_sync(0xffffffffu, s,  o);
        s2 += __shfl_xor_sync(0xffffffffu, s2, o);
    }
    float mean = s * (1.f / 256.f);
    float var  = s2 * (1.f / 256.f) - mean * mean;
    float rstd = rsqrtf(var + 1e-5f);
    float* orow = out + (size_t)m * DIM;
    #pragma unroll
    for (int k = 0; k < 8; k++) {
        int d = lane + 32 * k;
        orow[d] = ftrunc_tf((vals[k] - mean) * rstd * w[d] + b[d]);
    }
}

// ---------------- MMA flash attention, q-tile 128, 8 warps ----------------
__global__ void __launch_bounds__(256)
attn_mma(const float* __restrict__ scale_d) {
    __shared__ uint32_t Ks[32 * 36];
    __shared__ uint32_t Vs[32 * 40];
    __shared__ uint32_t Ps[8][16 * 36];

    const int bh = blockIdx.y;
    const int b = bh >> 3, h = bh & 7;
    const int tid = threadIdx.x;
    const int warp = tid >> 5, lane = tid & 31;
    const int gid = lane >> 2, tig = lane & 3;
    const int q0 = blockIdx.x * 128;
    const float* base = g_qkv + (size_t)b * NTOK * 768;
    const float sc = scale_d[h];

    const int i0 = q0 + warp * 16 + gid;
    const int i1 = i0 + 8;

    uint32_t qf[4][4];
    #pragma unroll
    for (int ks = 0; ks < 4; ks++) {
        int c = h * 32 + ks * 8 + tig;
        float v00 = 0.f, v10 = 0.f, v01 = 0.f, v11 = 0.f;
        if (i0 < NTOK) { v00 = base[(size_t)i0 * 768 + c] * sc;
                         v01 = base[(size_t)i0 * 768 + c + 4] * sc; }
        if (i1 < NTOK) { v10 = base[(size_t)i1 * 768 + c] * sc;
                         v11 = base[(size_t)i1 * 768 + c + 4] * sc; }
        qf[ks][0] = f2tf(v00); qf[ks][1] = f2tf(v10);
        qf[ks][2] = f2tf(v01); qf[ks][3] = f2tf(v11);
    }

    float m0 = -1e30f, m1 = -1e30f, l0 = 0.f, l1 = 0.f;
    float oacc[4][4] = {};

    const int jmax = min(q0 + 127, NTOK - 1);
    for (int j0 = 0; j0 < jmax; j0 += 32) {
        __syncthreads();
        {
            int r  = tid >> 3;
            int c4 = (tid & 7) * 4;
            int j  = j0 + r;
            if (j < NTOK) {
                const float* kp = base + (size_t)j * 768 + 256 + h * 32 + c4;
                const float* vp = base + (size_t)j * 768 + 512 + h * 32 + c4;
                float4 ka = *(const float4*)kp;
                Ks[r * 36 + c4 + 0] = f2tf(ka.x); Ks[r * 36 + c4 + 1] = f2tf(ka.y);
                Ks[r * 36 + c4 + 2] = f2tf(ka.z); Ks[r * 36 + c4 + 3] = f2tf(ka.w);
                float4 va = *(const float4*)vp;
                Vs[r * 40 + c4 + 0] = f2tf(va.x); Vs[r * 40 + c4 + 1] = f2tf(va.y);
                Vs[r * 40 + c4 + 2] = f2tf(va.z); Vs[r * 40 + c4 + 3] = f2tf(va.w);
            } else {
                #pragma unroll
                for (int q = 0; q < 4; q++) {
                    Ks[r * 36 + c4 + q] = 0;
                    Vs[r * 40 + c4 + q] = 0;
                }
            }
        }
        __syncthreads();

        float s[4][4] = {};
        #pragma unroll
        for (int ks = 0; ks < 4; ks++) {
            #pragma unroll
            for (int nt = 0; nt < 4; nt++) {
                uint32_t b0 = Ks[(nt * 8 + gid) * 36 + ks * 8 + tig];
                uint32_t b1 = Ks[(nt * 8 + gid) * 36 + ks * 8 + tig + 4];
                mma_tf32(s[nt], qf[ks], b0, b1);
            }
        }

        float rm0 = -1e30f, rm1 = -1e30f;
        #pragma unroll
        for (int nt = 0; nt < 4; nt++) {
            int jc = j0 + nt * 8 + tig * 2;
            if (jc     >= i0) s[nt][0] = -1e30f;
            if (jc + 1 >= i0) s[nt][1] = -1e30f;
            if (jc     >= i1) s[nt][2] = -1e30f;
            if (jc + 1 >= i1) s[nt][3] = -1e30f;
            rm0 = fmaxf(rm0, fmaxf(s[nt][0], s[nt][1]));
            rm1 = fmaxf(rm1, fmaxf(s[nt][2], s[nt][3]));
        }
        rm0 = fmaxf(rm0, __shfl_xor_sync(0xffffffffu, rm0, 1));
        rm0 = fmaxf(rm0, __shfl_xor_sync(0xffffffffu, rm0, 2));
        rm1 = fmaxf(rm1, __shfl_xor_sync(0xffffffffu, rm1, 1));
        rm1 = fmaxf(rm1, __shfl_xor_sync(0xffffffffu, rm1, 2));
        float mn0 = fmaxf(m0, rm0), mn1 = fmaxf(m1, rm1);
        float corr0 = __expf(m0 - mn0), corr1 = __expf(m1 - mn1);

        float p[4][4];
        float ps0 = 0.f, ps1 = 0.f;
        #pragma unroll
        for (int nt = 0; nt < 4; nt++) {
            p[nt][0] = (s[nt][0] < -1e29f) ? 0.f : __expf(s[nt][0] - mn0);
            p[nt][1] = (s[nt][1] < -1e29f) ? 0.f : __expf(s[nt][1] - mn0);
            p[nt][2] = (s[nt][2] < -1e29f) ? 0.f : __expf(s[nt][2] - mn1);
            p[nt][3] = (s[nt][3] < -1e29f) ? 0.f : __expf(s[nt][3] - mn1);
            ps0 += p[nt][0] + p[nt][1];
            ps1 += p[nt][2] + p[nt][3];
        }
        ps0 += __shfl_xor_sync(0xffffffffu, ps0, 1);
        ps0 += __shfl_xor_sync(0xffffffffu, ps0, 2);
        ps1 += __shfl_xor_sync(0xffffffffu, ps1, 1);
        ps1 += __shfl_xor_sync(0xffffffffu, ps1, 2);
        l0 = l0 * corr0 + ps0;
        l1 = l1 * corr1 + ps1;
        #pragma unroll
        for (int nt = 0; nt < 4; nt++) {
            oacc[nt][0] *= corr0; oacc[nt][1] *= corr0;
            oacc[nt][2] *= corr1; oacc[nt][3] *= corr1;
        }

        uint32_t* pw = Ps[warp];
        __syncwarp();
        #pragma unroll
        for (int nt = 0; nt < 4; nt++) {
            pw[gid * 36 + nt * 8 + tig * 2    ]  = f2tf(p[nt][0]);
            pw[gid * 36 + nt * 8 + tig * 2 + 1]  = f2tf(p[nt][1]);
            pw[(gid + 8) * 36 + nt * 8 + tig * 2    ] = f2tf(p[nt][2]);
            pw[(gid + 8) * 36 + nt * 8 + tig * 2 + 1] = f2tf(p[nt][3]);
        }
        __syncwarp();

        #pragma unroll
        for (int ks = 0; ks < 4; ks++) {
            uint32_t af[4];
            af[0] = pw[gid * 36 + ks * 8 + tig];
            af[1] = pw[(gid + 8) * 36 + ks * 8 + tig];
            af[2] = pw[gid * 36 + ks * 8 + tig + 4];
            af[3] = pw[(gid + 8) * 36 + ks * 8 + tig + 4];
            #pragma unroll
            for (int nt = 0; nt < 4; nt++) {
                uint32_t b0 = Vs[(ks * 8 + tig) * 40 + nt * 8 + gid];
                uint32_t b1 = Vs[(ks * 8 + tig + 4) * 40 + nt * 8 + gid];
                mma_tf32(oacc[nt], af, b0, b1);
            }
        }
        m0 = mn0; m1 = mn1;
    }

    float inv0 = (l0 > 0.f) ? 1.f / l0 : 0.f;
    float inv1 = (l1 > 0.f) ? 1.f / l1 : 0.f;
    #pragma unroll
    for (int nt = 0; nt < 4; nt++) {
        int col = h * 32 + nt * 8 + tig * 2;
        if (i0 < NTOK) {
            float2 o = make_float2(ftrunc_tf(oacc[nt][0] * inv0),
                                   ftrunc_tf(oacc[nt][1] * inv0));
            *(float2*)&g_attn[((size_t)b * NTOK + i0) * DIM + col] = o;
        }
        if (i1 < NTOK) {
            float2 o = make_float2(ftrunc_tf(oacc[nt][2] * inv1),
                                   ftrunc_tf(oacc[nt][3] * inv1));
            *(float2*)&g_attn[((size_t)b * NTOK + i1) * DIM + col] = o;
        }
    }
}

// ---------------- untokenize + crop ----------------------------------------
__global__ void reshape_kernel(const float* __restrict__ pix, float* __restrict__ out) {
    int idx = blockIdx.x * blockDim.x + threadIdx.x;
    const int total = BATCH * IMGS * IMGS;
    if (idx >= total) return;
    int b   = idx / (IMGS * IMGS);
    int rem = idx % (IMGS * IMGS);
    int y = rem / IMGS, x = rem % IMGS;
    int py = y >> 4, pr = y & 15, px = x >> 4, pc = x & 15;
    int m = b * NTOK + py * HP + px;
    out[idx] = pix[(size_t)m * 256 + pr * 16 + pc];
}

// ---------------- host orchestration ---------------------------------------
static inline dim3 gemm_grid(int M, int Nn) { return dim3((Nn + 127) / 128, (M + 127) / 128); }

extern "C" void kernel_launch(void* const* d_in, const int* in_sizes, int n_in,
                              void* d_out, int out_size) {
    const float* x      = (const float*)d_in[0];
    const float* pos    = (const float*)d_in[1];
    const float* spt_w  = (const float*)d_in[2];
    const float* spt_b  = (const float*)d_in[3];
    const float* ln1_w  = (const float*)d_in[4];
    const float* ln1_b  = (const float*)d_in[5];
    const float* scale  = (const float*)d_in[6];
    const float* wqkv   = (const float*)d_in[7];
    const float* wout   = (const float*)d_in[8];
    const float* bout   = (const float*)d_in[9];
    const float* ln2_w  = (const float*)d_in[10];
    const float* ln2_b  = (const float*)d_in[11];
    const float* ff1_w  = (const float*)d_in[12];
    const float* ff1_b  = (const float*)d_in[13];
    const float* ff2_w  = (const float*)d_in[14];
    const float* ff2_b  = (const float*)d_in[15];
    const float* pix_w  = (const float*)d_in[16];
    const float* pix_b  = (const float*)d_in[17];

    float *tok, *t, *ln, *qkv, *attn, *ff, *wtf;
    cudaGetSymbolAddress((void**)&tok,  g_tok);
    cudaGetSymbolAddress((void**)&t,    g_t);
    cudaGetSymbolAddress((void**)&ln,   g_ln);
    cudaGetSymbolAddress((void**)&qkv,  g_qkv);
    cudaGetSymbolAddress((void**)&attn, g_attn);
    cudaGetSymbolAddress((void**)&ff,   g_ff);
    cudaGetSymbolAddress((void**)&wtf,  g_wtf);

    cudaFuncSetAttribute(gemm_tc<0, true,  true,  true,  false>, cudaFuncAttributeMaxDynamicSharedMemorySize, GEMM_SMEM);
    cudaFuncSetAttribute(gemm_tc<0, false, false, false, false>, cudaFuncAttributeMaxDynamicSharedMemorySize, GEMM_SMEM);
    cudaFuncSetAttribute(gemm_tc<0, true,  true,  false, false>, cudaFuncAttributeMaxDynamicSharedMemorySize, GEMM_SMEM);
    cudaFuncSetAttribute(gemm_tc<1, true,  false, false, true >, cudaFuncAttributeMaxDynamicSharedMemorySize, GEMM_SMEM);
    cudaFuncSetAttribute(gemm_tc<0, true,  false, false, false>, cudaFuncAttributeMaxDynamicSharedMemorySize, GEMM_SMEM);

    convert_w<<<(W_TOTAL / 4 + 255) / 256, 256>>>(spt_w, wqkv, wout, ff1_w, ff2_w, pix_w);
    {
        int total = MTOK * 1280;
        tokenize_kernel<<<(total + 255) / 256, 256>>>(x);
    }
    gemm_tc<0, true, true, true, false><<<gemm_grid(MTOK, DIM), 128, GEMM_SMEM>>>(
        tok, wtf + W_SPT_OFF, spt_b, pos, t, MTOK, DIM, 1280);

    const int LN_BLOCKS = (MTOK + 7) / 8;
    for (int d = 0; d < 3; d++) {
        ln_kernel<<<LN_BLOCKS, 256>>>(t, ln1_w + d * DIM, ln1_b + d * DIM, ln);
        gemm_tc<0, false, false, false, false><<<gemm_grid(MTOK, 768), 128, GEMM_SMEM>>>(
            ln, wtf + W_QKV_OFF + (size_t)d * 768 * DIM, nullptr, nullptr, qkv, MTOK, 768, DIM);
        {
            dim3 grid((NTOK + 127) / 128, BATCH * NHEADS);
            attn_mma<<<grid, 256>>>(scale + d * NHEADS);
        }
        gemm_tc<0, true, true, false, false><<<gemm_grid(MTOK, DIM), 128, GEMM_SMEM>>>(
            attn, wtf + W_WOUT_OFF + (size_t)d * DIM * DIM, bout + d * DIM, t, t, MTOK, DIM, DIM);
        ln_kernel<<<LN_BLOCKS, 256>>>(t, ln2_w + d * DIM, ln2_b + d * DIM, ln);
        gemm_tc<1, true, false, false, true><<<gemm_grid(MTOK, 1024), 128, GEMM_SMEM>>>(
            ln, wtf + W_FF1_OFF + (size_t)d * 1024 * DIM, ff1_b + d * 1024, nullptr, ff, MTOK, 1024, DIM);
        gemm_tc<0, true, true, false, false><<<gemm_grid(MTOK, DIM), 128, GEMM_SMEM>>>(
            ff, wtf + W_FF2_OFF + (size_t)d * DIM * 1024, ff2_b + d * DIM, t, t, MTOK, DIM, 1024);
    }

    gemm_tc<0, true, false, false, false><<<gemm_grid(MTOK, DIM), 128, GEMM_SMEM>>>(
        t, wtf + W_PIX_OFF, pix_b, nullptr, qkv, MTOK, DIM, DIM);

    {
        int total = BATCH * IMGS * IMGS;
        reshape_kernel<<<(total + 255) / 256, 256>>>(qkv, (float*)d_out);
    }
}

// round 9
// speedup vs baseline: 1.2181x; 1.2181x over previous
#include <cuda_runtime.h>
#include <math.h>
#include <stdint.h>

#define IMGS   457
#define HPAD   464
#define HP     29
#define NTOK   841
#define BATCH  8
#define DIM    256
#define MTOK   (BATCH*NTOK)   // 6728
#define NHEADS 8
#define DH     32

// ---------------- scratch (device globals; no allocations) ----------------
__device__ float g_tok [MTOK*1280];
__device__ float g_t   [MTOK*DIM];
__device__ float g_ln  [MTOK*DIM];
__device__ float g_qkv [MTOK*768];
__device__ float g_attn[MTOK*DIM];
__device__ float g_ff  [MTOK*1024];

// pre-truncated (tf32) weights
#define W_SPT_OFF  0
#define W_SPT_SZ   (256*1280)
#define W_QKV_OFF  (W_SPT_OFF+W_SPT_SZ)
#define W_QKV_SZ   (3*768*256)
#define W_WOUT_OFF (W_QKV_OFF+W_QKV_SZ)
#define W_WOUT_SZ  (3*256*256)
#define W_FF1_OFF  (W_WOUT_OFF+W_WOUT_SZ)
#define W_FF1_SZ   (3*1024*256)
#define W_FF2_OFF  (W_FF1_OFF+W_FF1_SZ)
#define W_FF2_SZ   (3*256*1024)
#define W_PIX_OFF  (W_FF2_OFF+W_FF2_SZ)
#define W_PIX_SZ   (256*256)
#define W_TOTAL    (W_PIX_OFF+W_PIX_SZ)
__device__ float g_wtf[W_TOTAL];

__device__ __forceinline__ uint32_t f2tf(float f) {
    uint32_t r;
    asm("cvt.rna.tf32.f32 %0, %1;" : "=r"(r) : "f"(f));
    return r;
}
__device__ __forceinline__ float ftrunc_tf(float f) { return __uint_as_float(f2tf(f)); }

__global__ void convert_w(const float* __restrict__ spt, const float* __restrict__ qkv,
                          const float* __restrict__ wo, const float* __restrict__ f1,
                          const float* __restrict__ f2w, const float* __restrict__ px) {
    int i4 = blockIdx.x * 256 + threadIdx.x;
    if (i4 >= W_TOTAL / 4) return;
    int i = i4 * 4;
    const float* src; int off;
    if      (i < W_QKV_OFF)  { src = spt; off = 0; }
    else if (i < W_WOUT_OFF) { src = qkv; off = W_QKV_OFF; }
    else if (i < W_FF1_OFF)  { src = wo;  off = W_WOUT_OFF; }
    else if (i < W_FF2_OFF)  { src = f1;  off = W_FF1_OFF; }
    else if (i < W_PIX_OFF)  { src = f2w; off = W_FF2_OFF; }
    else                     { src = px;  off = W_PIX_OFF; }
    float4 v = *(const float4*)(src + (i - off));
    v.x = ftrunc_tf(v.x); v.y = ftrunc_tf(v.y);
    v.z = ftrunc_tf(v.z); v.w = ftrunc_tf(v.w);
    *(float4*)&g_wtf[i] = v;
}

// ---------------- tokenize: pad + 5 shifted rolls + patchify --------------
__global__ void tokenize_kernel(const float* __restrict__ x) {
    int idx = blockIdx.x * blockDim.x + threadIdx.x;
    const int total = MTOK * 1280;
    if (idx >= total) return;
    int c = idx % 1280;
    int m = idx / 1280;
    int b = m / NTOK;
    int n = m % NTOK;
    int py = n / HP, px = n % HP;
    int s  = c / 256;
    int pr = (c % 256) / 16;
    int pc = c % 16;
    const int dxs[5] = {0, -8, 8, -8, 8};
    const int dys[5] = {0, -8, -8, 8, 8};
    int y  = py * 16 + pr - dys[s];
    int xx = px * 16 + pc - dxs[s];
    y  = (y  + HPAD) % HPAD;
    xx = (xx + HPAD) % HPAD;
    float v = 0.f;
    if (y < IMGS && xx < IMGS)
        v = x[((size_t)b * IMGS + y) * IMGS + xx];
    g_tok[idx] = ftrunc_tf(v);
}

// ---------------- tf32 tensor-core GEMM, 3-stage cp.async, LDSM frags -----
__device__ __forceinline__ void mma_tf32(float c[4], const uint32_t a[4],
                                         uint32_t b0, uint32_t b1) {
    asm volatile(
        "mma.sync.aligned.m16n8k8.row.col.f32.tf32.tf32.f32 "
        "{%0,%1,%2,%3}, {%4,%5,%6,%7}, {%8,%9}, {%0,%1,%2,%3};"
        : "+f"(c[0]), "+f"(c[1]), "+f"(c[2]), "+f"(c[3])
        : "r"(a[0]), "r"(a[1]), "r"(a[2]), "r"(a[3]), "r"(b0), "r"(b1));
}
__device__ __forceinline__ float gelu_exact(float v) {
    return 0.5f * v * (1.0f + erff(v * 0.70710678118654752440f));
}
__device__ __forceinline__ void cp16(uint32_t saddr, const float* g, bool pred) {
    asm volatile("cp.async.cg.shared.global [%0], [%1], 16, %2;"
                 :: "r"(saddr), "l"(g), "r"(pred ? 16 : 0));
}
__device__ __forceinline__ void cp_commit() { asm volatile("cp.async.commit_group;"); }
template<int N>
__device__ __forceinline__ void cp_wait() {
    asm volatile("cp.async.wait_group %0;" :: "n"(N));
}
__device__ __forceinline__ int swz(int row, int col) {
    return row * 32 + (col ^ ((row & 7) * 4));
}
__device__ __forceinline__ void ldsm4(uint32_t addr, uint32_t& r0, uint32_t& r1,
                                      uint32_t& r2, uint32_t& r3) {
    asm volatile("ldmatrix.sync.aligned.m8n8.x4.shared.b16 {%0,%1,%2,%3}, [%4];"
                 : "=r"(r0), "=r"(r1), "=r"(r2), "=r"(r3) : "r"(addr));
}

#define GEMM_SMEM (6 * 4096 * 4)   // 3 stages x (A 128x32 + W 128x32) floats

template<int ACT, bool HASBIAS, bool HASRES, bool POSMOD, bool TRUNC>
__global__ void __launch_bounds__(256)
gemm_tc(const float* __restrict__ A, const float* __restrict__ W,
        const float* __restrict__ bias, const float* __restrict__ res,
        float* __restrict__ C, int M, int Nn, int K) {
    extern __shared__ float smem[];
    float* As = smem;               // [3][128*32]
    float* Ws = smem + 3 * 4096;    // [3][128*32]
    const int tid  = threadIdx.x;
    const int wid  = tid >> 5, lane = tid & 31;
    const int wm   = wid & 3,  wn   = wid >> 2;
    const int gid  = lane >> 2, tig = lane & 3;
    const int m0   = blockIdx.y * 128, n0 = blockIdx.x * 128;

    const int lrow = tid >> 3;
    const int lc4  = (tid & 7) * 4;

    uint32_t As_base = (uint32_t)__cvta_generic_to_shared(As);
    uint32_t Ws_base = (uint32_t)__cvta_generic_to_shared(Ws);

    // per-lane LDSM addressing (constant across k-steps except ks offset)
    const int rowA_in  = (lane & 15);              // row within 16-row frag block
    const int koffA    = ((lane >> 4) & 1) * 4;    // k-granule select
    const int rowB_in  = (lane & 7) + (((lane >> 4) & 1) << 3);
    const int koffB    = ((lane >> 3) & 1) * 4;

    float acc[2][8][4] = {};
    const int ktiles = K >> 5;

    auto load_tile = [&](int kt, int buf) {
        const float* Ag = A + (size_t)m0 * K + kt * 32;
        #pragma unroll
        for (int i = 0; i < 4; i++) {
            int row = lrow + i * 32;
            uint32_t s = As_base + (buf * 4096 + swz(row, lc4)) * 4;
            cp16(s, Ag + (size_t)row * K + lc4, (m0 + row) < M);
        }
        const float* Wg = W + (size_t)n0 * K + kt * 32;
        #pragma unroll
        for (int i = 0; i < 4; i++) {
            int row = lrow + i * 32;
            uint32_t s = Ws_base + (buf * 4096 + swz(row, lc4)) * 4;
            cp16(s, Wg + (size_t)row * K + lc4, true);
        }
    };

    load_tile(0, 0);
    cp_commit();
    if (ktiles > 1) { load_tile(1, 1); cp_commit(); }

    for (int kt = 0; kt < ktiles; kt++) {
        if (kt + 2 < ktiles) {
            load_tile(kt + 2, (kt + 2) % 3);
            cp_commit();
            cp_wait<2>();
        } else if (kt + 1 < ktiles) {
            cp_wait<1>();
        } else {
            cp_wait<0>();
        }
        __syncthreads();

        const uint32_t as_b = As_base + ((kt % 3) * 4096) * 4;
        const uint32_t ws_b = Ws_base + ((kt % 3) * 4096) * 4;
        #pragma unroll
        for (int ks = 0; ks < 32; ks += 8) {
            uint32_t af[2][4];
            #pragma unroll
            for (int mt = 0; mt < 2; mt++) {
                int row = wm * 32 + mt * 16 + rowA_in;
                int col = ks + koffA;
                uint32_t addr = as_b + (uint32_t)swz(row, col) * 4;
                ldsm4(addr, af[mt][0], af[mt][1], af[mt][2], af[mt][3]);
            }
            #pragma unroll
            for (int np = 0; np < 4; np++) {
                int row = wn * 64 + np * 16 + rowB_in;
                int col = ks + koffB;
                uint32_t addr = ws_b + (uint32_t)swz(row, col) * 4;
                uint32_t b0a, b1a, b0b, b1b;
                ldsm4(addr, b0a, b1a, b0b, b1b);
                mma_tf32(acc[0][2 * np    ], af[0], b0a, b1a);
                mma_tf32(acc[1][2 * np    ], af[1], b0a, b1a);
                mma_tf32(acc[0][2 * np + 1], af[0], b0b, b1b);
                mma_tf32(acc[1][2 * np + 1], af[1], b0b, b1b);
            }
        }
        __syncthreads();
    }

    #pragma unroll
    for (int mt = 0; mt < 2; mt++) {
        #pragma unroll
        for (int half = 0; half < 2; half++) {
            int m = m0 + wm * 32 + mt * 16 + gid + half * 8;
            if (m >= M) continue;
            int mres = POSMOD ? (m % NTOK) : m;
            #pragma unroll
            for (int nt = 0; nt < 8; nt++) {
                int n = n0 + wn * 64 + nt * 8 + tig * 2;
                float v0 = acc[mt][nt][half * 2 + 0];
                float v1 = acc[mt][nt][half * 2 + 1];
                if (HASBIAS) { v0 += bias[n]; v1 += bias[n + 1]; }
                if (ACT == 1) { v0 = gelu_exact(v0); v1 = gelu_exact(v1); }
                if (HASRES) {
                    float2 r = *(const float2*)&res[(size_t)mres * Nn + n];
                    v0 += r.x; v1 += r.y;
                }
                if (TRUNC) { v0 = ftrunc_tf(v0); v1 = ftrunc_tf(v1); }
                *(float2*)&C[(size_t)m * Nn + n] = make_float2(v0, v1);
            }
        }
    }
}

// ---------------- LayerNorm (warp per token, dim=256, tf32-truncated out) --
__global__ void ln_kernel(const float* __restrict__ in, const float* __restrict__ w,
                          const float* __restrict__ b, float* __restrict__ out) {
    int warp = threadIdx.x / 32, lane = threadIdx.x % 32;
    int m = blockIdx.x * 8 + warp;
    if (m >= MTOK) return;
    const float* row = in + (size_t)m * DIM;
    float vals[8], s = 0.f, s2 = 0.f;
    #pragma unroll
    for (int k = 0; k < 8; k++) {
        float v = row[lane + 32 * k];
        vals[k] = v; s += v; s2 += v * v;
    }
    #pragma unroll
    for (int o = 16; o; o >>= 1) {
        s  += __shfl_xor_sync(0xffffffffu, s,  o);
        s2 += __shfl_xor_sync(0xffffffffu, s2, o);
    }
    float mean = s * (1.f / 256.f);
    float var  = s2 * (1.f / 256.f) - mean * mean;
    float rstd = rsqrtf(var + 1e-5f);
    float* orow = out + (size_t)m * DIM;
    #pragma unroll
    for (int k = 0; k < 8; k++) {
        int d = lane + 32 * k;
        orow[d] = ftrunc_tf((vals[k] - mean) * rstd * w[d] + b[d]);
    }
}

// ---------------- MMA flash attention, q-tile 128, 8 warps ----------------
__global__ void __launch_bounds__(256)
attn_mma(const float* __restrict__ scale_d) {
    __shared__ uint32_t Ks[32 * 36];
    __shared__ uint32_t Vs[32 * 40];
    __shared__ uint32_t Ps[8][16 * 36];

    const int bh = blockIdx.y;
    const int b = bh >> 3, h = bh & 7;
    const int tid = threadIdx.x;
    const int warp = tid >> 5, lane = tid & 31;
    const int gid = lane >> 2, tig = lane & 3;
    const int q0 = blockIdx.x * 128;
    const float* base = g_qkv + (size_t)b * NTOK * 768;
    const float sc = scale_d[h];

    const int i0 = q0 + warp * 16 + gid;
    const int i1 = i0 + 8;

    uint32_t qf[4][4];
    #pragma unroll
    for (int ks = 0; ks < 4; ks++) {
        int c = h * 32 + ks * 8 + tig;
        float v00 = 0.f, v10 = 0.f, v01 = 0.f, v11 = 0.f;
        if (i0 < NTOK) { v00 = base[(size_t)i0 * 768 + c] * sc;
                         v01 = base[(size_t)i0 * 768 + c + 4] * sc; }
        if (i1 < NTOK) { v10 = base[(size_t)i1 * 768 + c] * sc;
                         v11 = base[(size_t)i1 * 768 + c + 4] * sc; }
        qf[ks][0] = f2tf(v00); qf[ks][1] = f2tf(v10);
        qf[ks][2] = f2tf(v01); qf[ks][3] = f2tf(v11);
    }

    float m0 = -1e30f, m1 = -1e30f, l0 = 0.f, l1 = 0.f;
    float oacc[4][4] = {};

    const int jmax = min(q0 + 127, NTOK - 1);
    for (int j0 = 0; j0 < jmax; j0 += 32) {
        __syncthreads();
        {
            int r  = tid >> 3;
            int c4 = (tid & 7) * 4;
            int j  = j0 + r;
            if (j < NTOK) {
                const float* kp = base + (size_t)j * 768 + 256 + h * 32 + c4;
                const float* vp = base + (size_t)j * 768 + 512 + h * 32 + c4;
                float4 ka = *(const float4*)kp;
                Ks[r * 36 + c4 + 0] = f2tf(ka.x); Ks[r * 36 + c4 + 1] = f2tf(ka.y);
                Ks[r * 36 + c4 + 2] = f2tf(ka.z); Ks[r * 36 + c4 + 3] = f2tf(ka.w);
                float4 va = *(const float4*)vp;
                Vs[r * 40 + c4 + 0] = f2tf(va.x); Vs[r * 40 + c4 + 1] = f2tf(va.y);
                Vs[r * 40 + c4 + 2] = f2tf(va.z); Vs[r * 40 + c4 + 3] = f2tf(va.w);
            } else {
                #pragma unroll
                for (int q = 0; q < 4; q++) {
                    Ks[r * 36 + c4 + q] = 0;
                    Vs[r * 40 + c4 + q] = 0;
                }
            }
        }
        __syncthreads();

        float s[4][4] = {};
        #pragma unroll
        for (int ks = 0; ks < 4; ks++) {
            #pragma unroll
            for (int nt = 0; nt < 4; nt++) {
                uint32_t b0 = Ks[(nt * 8 + gid) * 36 + ks * 8 + tig];
                uint32_t b1 = Ks[(nt * 8 + gid) * 36 + ks * 8 + tig + 4];
                mma_tf32(s[nt], qf[ks], b0, b1);
            }
        }

        float rm0 = -1e30f, rm1 = -1e30f;
        #pragma unroll
        for (int nt = 0; nt < 4; nt++) {
            int jc = j0 + nt * 8 + tig * 2;
            if (jc     >= i0) s[nt][0] = -1e30f;
            if (jc + 1 >= i0) s[nt][1] = -1e30f;
            if (jc     >= i1) s[nt][2] = -1e30f;
            if (jc + 1 >= i1) s[nt][3] = -1e30f;
            rm0 = fmaxf(rm0, fmaxf(s[nt][0], s[nt][1]));
            rm1 = fmaxf(rm1, fmaxf(s[nt][2], s[nt][3]));
        }
        rm0 = fmaxf(rm0, __shfl_xor_sync(0xffffffffu, rm0, 1));
        rm0 = fmaxf(rm0, __shfl_xor_sync(0xffffffffu, rm0, 2));
        rm1 = fmaxf(rm1, __shfl_xor_sync(0xffffffffu, rm1, 1));
        rm1 = fmaxf(rm1, __shfl_xor_sync(0xffffffffu, rm1, 2));
        float mn0 = fmaxf(m0, rm0), mn1 = fmaxf(m1, rm1);
        float corr0 = __expf(m0 - mn0), corr1 = __expf(m1 - mn1);

        float p[4][4];
        float ps0 = 0.f, ps1 = 0.f;
        #pragma unroll
        for (int nt = 0; nt < 4; nt++) {
            p[nt][0] = (s[nt][0] < -1e29f) ? 0.f : __expf(s[nt][0] - mn0);
            p[nt][1] = (s[nt][1] < -1e29f) ? 0.f : __expf(s[nt][1] - mn0);
            p[nt][2] = (s[nt][2] < -1e29f) ? 0.f : __expf(s[nt][2] - mn1);
            p[nt][3] = (s[nt][3] < -1e29f) ? 0.f : __expf(s[nt][3] - mn1);
            ps0 += p[nt][0] + p[nt][1];
            ps1 += p[nt][2] + p[nt][3];
        }
        ps0 += __shfl_xor_sync(0xffffffffu, ps0, 1);
        ps0 += __shfl_xor_sync(0xffffffffu, ps0, 2);
        ps1 += __shfl_xor_sync(0xffffffffu, ps1, 1);
        ps1 += __shfl_xor_sync(0xffffffffu, ps1, 2);
        l0 = l0 * corr0 + ps0;
        l1 = l1 * corr1 + ps1;
        #pragma unroll
        for (int nt = 0; nt < 4; nt++) {
            oacc[nt][0] *= corr0; oacc[nt][1] *= corr0;
            oacc[nt][2] *= corr1; oacc[nt][3] *= corr1;
        }

        uint32_t* pw = Ps[warp];
        __syncwarp();
        #pragma unroll
        for (int nt = 0; nt < 4; nt++) {
            pw[gid * 36 + nt * 8 + tig * 2    ]  = f2tf(p[nt][0]);
            pw[gid * 36 + nt * 8 + tig * 2 + 1]  = f2tf(p[nt][1]);
            pw[(gid + 8) * 36 + nt * 8 + tig * 2    ] = f2tf(p[nt][2]);
            pw[(gid + 8) * 36 + nt * 8 + tig * 2 + 1] = f2tf(p[nt][3]);
        }
        __syncwarp();

        #pragma unroll
        for (int ks = 0; ks < 4; ks++) {
            uint32_t af[4];
            af[0] = pw[gid * 36 + ks * 8 + tig];
            af[1] = pw[(gid + 8) * 36 + ks * 8 + tig];
            af[2] = pw[gid * 36 + ks * 8 + tig + 4];
            af[3] = pw[(gid + 8) * 36 + ks * 8 + tig + 4];
            #pragma unroll
            for (int nt = 0; nt < 4; nt++) {
                uint32_t b0 = Vs[(ks * 8 + tig) * 40 + nt * 8 + gid];
                uint32_t b1 = Vs[(ks * 8 + tig + 4) * 40 + nt * 8 + gid];
                mma_tf32(oacc[nt], af, b0, b1);
            }
        }
        m0 = mn0; m1 = mn1;
    }

    float inv0 = (l0 > 0.f) ? 1.f / l0 : 0.f;
    float inv1 = (l1 > 0.f) ? 1.f / l1 : 0.f;
    #pragma unroll
    for (int nt = 0; nt < 4; nt++) {
        int col = h * 32 + nt * 8 + tig * 2;
        if (i0 < NTOK) {
            float2 o = make_float2(ftrunc_tf(oacc[nt][0] * inv0),
                                   ftrunc_tf(oacc[nt][1] * inv0));
            *(float2*)&g_attn[((size_t)b * NTOK + i0) * DIM + col] = o;
        }
        if (i1 < NTOK) {
            float2 o = make_float2(ftrunc_tf(oacc[nt][2] * inv1),
                                   ftrunc_tf(oacc[nt][3] * inv1));
            *(float2*)&g_attn[((size_t)b * NTOK + i1) * DIM + col] = o;
        }
    }
}

// ---------------- untokenize + crop ----------------------------------------
__global__ void reshape_kernel(const float* __restrict__ pix, float* __restrict__ out) {
    int idx = blockIdx.x * blockDim.x + threadIdx.x;
    const int total = BATCH * IMGS * IMGS;
    if (idx >= total) return;
    int b   = idx / (IMGS * IMGS);
    int rem = idx % (IMGS * IMGS);
    int y = rem / IMGS, x = rem % IMGS;
    int py = y >> 4, pr = y & 15, px = x >> 4, pc = x & 15;
    int m = b * NTOK + py * HP + px;
    out[idx] = pix[(size_t)m * 256 + pr * 16 + pc];
}

// ---------------- host orchestration ---------------------------------------
static inline dim3 gemm_grid(int M, int Nn) { return dim3((Nn + 127) / 128, (M + 127) / 128); }

extern "C" void kernel_launch(void* const* d_in, const int* in_sizes, int n_in,
                              void* d_out, int out_size) {
    const float* x      = (const float*)d_in[0];
    const float* pos    = (const float*)d_in[1];
    const float* spt_w  = (const float*)d_in[2];
    const float* spt_b  = (const float*)d_in[3];
    const float* ln1_w  = (const float*)d_in[4];
    const float* ln1_b  = (const float*)d_in[5];
    const float* scale  = (const float*)d_in[6];
    const float* wqkv   = (const float*)d_in[7];
    const float* wout   = (const float*)d_in[8];
    const float* bout   = (const float*)d_in[9];
    const float* ln2_w  = (const float*)d_in[10];
    const float* ln2_b  = (const float*)d_in[11];
    const float* ff1_w  = (const float*)d_in[12];
    const float* ff1_b  = (const float*)d_in[13];
    const float* ff2_w  = (const float*)d_in[14];
    const float* ff2_b  = (const float*)d_in[15];
    const float* pix_w  = (const float*)d_in[16];
    const float* pix_b  = (const float*)d_in[17];

    float *tok, *t, *ln, *qkv, *attn, *ff, *wtf;
    cudaGetSymbolAddress((void**)&tok,  g_tok);
    cudaGetSymbolAddress((void**)&t,    g_t);
    cudaGetSymbolAddress((void**)&ln,   g_ln);
    cudaGetSymbolAddress((void**)&qkv,  g_qkv);
    cudaGetSymbolAddress((void**)&attn, g_attn);
    cudaGetSymbolAddress((void**)&ff,   g_ff);
    cudaGetSymbolAddress((void**)&wtf,  g_wtf);

    cudaFuncSetAttribute(gemm_tc<0, true,  true,  true,  false>, cudaFuncAttributeMaxDynamicSharedMemorySize, GEMM_SMEM);
    cudaFuncSetAttribute(gemm_tc<0, false, false, false, false>, cudaFuncAttributeMaxDynamicSharedMemorySize, GEMM_SMEM);
    cudaFuncSetAttribute(gemm_tc<0, true,  true,  false, false>, cudaFuncAttributeMaxDynamicSharedMemorySize, GEMM_SMEM);
    cudaFuncSetAttribute(gemm_tc<1, true,  false, false, true >, cudaFuncAttributeMaxDynamicSharedMemorySize, GEMM_SMEM);
    cudaFuncSetAttribute(gemm_tc<0, true,  false, false, false>, cudaFuncAttributeMaxDynamicSharedMemorySize, GEMM_SMEM);

    convert_w<<<(W_TOTAL / 4 + 255) / 256, 256>>>(spt_w, wqkv, wout, ff1_w, ff2_w, pix_w);
    {
        int total = MTOK * 1280;
        tokenize_kernel<<<(total + 255) / 256, 256>>>(x);
    }
    gemm_tc<0, true, true, true, false><<<gemm_grid(MTOK, DIM), 256, GEMM_SMEM>>>(
        tok, wtf + W_SPT_OFF, spt_b, pos, t, MTOK, DIM, 1280);

    const int LN_BLOCKS = (MTOK + 7) / 8;
    for (int d = 0; d < 3; d++) {
        ln_kernel<<<LN_BLOCKS, 256>>>(t, ln1_w + d * DIM, ln1_b + d * DIM, ln);
        gemm_tc<0, false, false, false, false><<<gemm_grid(MTOK, 768), 256, GEMM_SMEM>>>(
            ln, wtf + W_QKV_OFF + (size_t)d * 768 * DIM, nullptr, nullptr, qkv, MTOK, 768, DIM);
        {
            dim3 grid((NTOK + 127) / 128, BATCH * NHEADS);
            attn_mma<<<grid, 256>>>(scale + d * NHEADS);
        }
        gemm_tc<0, true, true, false, false><<<gemm_grid(MTOK, DIM), 256, GEMM_SMEM>>>(
            attn, wtf + W_WOUT_OFF + (size_t)d * DIM * DIM, bout + d * DIM, t, t, MTOK, DIM, DIM);
        ln_kernel<<<LN_BLOCKS, 256>>>(t, ln2_w + d * DIM, ln2_b + d * DIM, ln);
        gemm_tc<1, true, false, false, true><<<gemm_grid(MTOK, 1024), 256, GEMM_SMEM>>>(
            ln, wtf + W_FF1_OFF + (size_t)d * 1024 * DIM, ff1_b + d * 1024, nullptr, ff, MTOK, 1024, DIM);
        gemm_tc<0, true, true, false, false><<<gemm_grid(MTOK, DIM), 256, GEMM_SMEM>>>(
            ff, wtf + W_FF2_OFF + (size_t)d * DIM * 1024, ff2_b + d * DIM, t, t, MTOK, DIM, 1024);
    }

    gemm_tc<0, true, false, false, false><<<gemm_grid(MTOK, DIM), 256, GEMM_SMEM>>>(
        t, wtf + W_PIX_OFF, pix_b, nullptr, qkv, MTOK, DIM, DIM);

    {
        int total = BATCH * IMGS * IMGS;
        reshape_kernel<<<(total + 255) / 256, 256>>>(qkv, (float*)d_out);
    }
}

// round 10
// speedup vs baseline: 1.2497x; 1.0259x over previous
#include <cuda_runtime.h>
#include <math.h>
#include <stdint.h>

#define IMGS   457
#define HPAD   464
#define HP     29
#define NTOK   841
#define BATCH  8
#define DIM    256
#define MTOK   (BATCH*NTOK)   // 6728
#define NHEADS 8
#define DH     32

// ---------------- scratch (device globals; no allocations) ----------------
__device__ float g_tok [MTOK*1280];
__device__ float g_t   [MTOK*DIM];
__device__ float g_ln  [MTOK*DIM];
__device__ float g_qkv [MTOK*768];
__device__ float g_attn[MTOK*DIM];
__device__ float g_ff  [MTOK*1024];

// pre-truncated (tf32) weights
#define W_SPT_OFF  0
#define W_SPT_SZ   (256*1280)
#define W_QKV_OFF  (W_SPT_OFF+W_SPT_SZ)
#define W_QKV_SZ   (3*768*256)
#define W_WOUT_OFF (W_QKV_OFF+W_QKV_SZ)
#define W_WOUT_SZ  (3*256*256)
#define W_FF1_OFF  (W_WOUT_OFF+W_WOUT_SZ)
#define W_FF1_SZ   (3*1024*256)
#define W_FF2_OFF  (W_FF1_OFF+W_FF1_SZ)
#define W_FF2_SZ   (3*256*1024)
#define W_PIX_OFF  (W_FF2_OFF+W_FF2_SZ)
#define W_PIX_SZ   (256*256)
#define W_TOTAL    (W_PIX_OFF+W_PIX_SZ)
__device__ float g_wtf[W_TOTAL];

__device__ __forceinline__ uint32_t f2tf(float f) {
    uint32_t r;
    asm("cvt.rna.tf32.f32 %0, %1;" : "=r"(r) : "f"(f));
    return r;
}
__device__ __forceinline__ float ftrunc_tf(float f) { return __uint_as_float(f2tf(f)); }

__global__ void convert_w(const float* __restrict__ spt, const float* __restrict__ qkv,
                          const float* __restrict__ wo, const float* __restrict__ f1,
                          const float* __restrict__ f2w, const float* __restrict__ px) {
    int i4 = blockIdx.x * 256 + threadIdx.x;
    if (i4 >= W_TOTAL / 4) return;
    int i = i4 * 4;
    const float* src; int off;
    if      (i < W_QKV_OFF)  { src = spt; off = 0; }
    else if (i < W_WOUT_OFF) { src = qkv; off = W_QKV_OFF; }
    else if (i < W_FF1_OFF)  { src = wo;  off = W_WOUT_OFF; }
    else if (i < W_FF2_OFF)  { src = f1;  off = W_FF1_OFF; }
    else if (i < W_PIX_OFF)  { src = f2w; off = W_FF2_OFF; }
    else                     { src = px;  off = W_PIX_OFF; }
    float4 v = *(const float4*)(src + (i - off));
    v.x = ftrunc_tf(v.x); v.y = ftrunc_tf(v.y);
    v.z = ftrunc_tf(v.z); v.w = ftrunc_tf(v.w);
    *(float4*)&g_wtf[i] = v;
}

// ---------------- tokenize: pad + 5 shifted rolls + patchify --------------
__global__ void tokenize_kernel(const float* __restrict__ x) {
    int idx = blockIdx.x * blockDim.x + threadIdx.x;
    const int total = MTOK * 1280;
    if (idx >= total) return;
    int c = idx % 1280;
    int m = idx / 1280;
    int b = m / NTOK;
    int n = m % NTOK;
    int py = n / HP, px = n % HP;
    int s  = c / 256;
    int pr = (c % 256) / 16;
    int pc = c % 16;
    const int dxs[5] = {0, -8, 8, -8, 8};
    const int dys[5] = {0, -8, -8, 8, 8};
    int y  = py * 16 + pr - dys[s];
    int xx = px * 16 + pc - dxs[s];
    y  = (y  + HPAD) % HPAD;
    xx = (xx + HPAD) % HPAD;
    float v = 0.f;
    if (y < IMGS && xx < IMGS)
        v = x[((size_t)b * IMGS + y) * IMGS + xx];
    g_tok[idx] = ftrunc_tf(v);
}

// ---------------- tf32 tensor-core GEMM, 3-stage cp.async, LDSM frags -----
// Template BM in {64,128}; BN=128 fixed; 256 threads.
__device__ __forceinline__ void mma_tf32(float c[4], const uint32_t a[4],
                                         uint32_t b0, uint32_t b1) {
    asm volatile(
        "mma.sync.aligned.m16n8k8.row.col.f32.tf32.tf32.f32 "
        "{%0,%1,%2,%3}, {%4,%5,%6,%7}, {%8,%9}, {%0,%1,%2,%3};"
        : "+f"(c[0]), "+f"(c[1]), "+f"(c[2]), "+f"(c[3])
        : "r"(a[0]), "r"(a[1]), "r"(a[2]), "r"(a[3]), "r"(b0), "r"(b1));
}
__device__ __forceinline__ float gelu_exact(float v) {
    return 0.5f * v * (1.0f + erff(v * 0.70710678118654752440f));
}
__device__ __forceinline__ void cp16(uint32_t saddr, const float* g, bool pred) {
    asm volatile("cp.async.cg.shared.global [%0], [%1], 16, %2;"
                 :: "r"(saddr), "l"(g), "r"(pred ? 16 : 0));
}
__device__ __forceinline__ void cp_commit() { asm volatile("cp.async.commit_group;"); }
template<int N>
__device__ __forceinline__ void cp_wait() {
    asm volatile("cp.async.wait_group %0;" :: "n"(N));
}
__device__ __forceinline__ int swz(int row, int col) {
    return row * 32 + (col ^ ((row & 7) * 4));
}
__device__ __forceinline__ void ldsm4(uint32_t addr, uint32_t& r0, uint32_t& r1,
                                      uint32_t& r2, uint32_t& r3) {
    asm volatile("ldmatrix.sync.aligned.m8n8.x4.shared.b16 {%0,%1,%2,%3}, [%4];"
                 : "=r"(r0), "=r"(r1), "=r"(r2), "=r"(r3) : "r"(addr));
}

#define GEMM_SMEM(BM) (3 * ((BM) * 32 + 4096) * 4)

template<int BM, int ACT, bool HASBIAS, bool HASRES, bool POSMOD, bool TRUNC>
__global__ void __launch_bounds__(256)
gemm_tc(const float* __restrict__ A, const float* __restrict__ W,
        const float* __restrict__ bias, const float* __restrict__ res,
        float* __restrict__ C, int M, int Nn, int K) {
    constexpr int NWM = BM / 32;        // m-warps (4 or 2)
    constexpr int NWN = 8 / NWM;        // n-warps (2 or 4)
    constexpr int WN  = 128 / NWN;      // warp n-extent (64 or 32)
    constexpr int NP  = WN / 16;        // B-LDSM per ks (4 or 2)
    constexpr int NT  = WN / 8;         // n-frags (8 or 4)
    constexpr int ASTG = BM * 32;       // A stage floats

    extern __shared__ float smem[];
    float* As = smem;                   // [3][ASTG]
    float* Ws = smem + 3 * ASTG;        // [3][4096]
    const int tid  = threadIdx.x;
    const int wid  = tid >> 5, lane = tid & 31;
    const int wm   = wid % NWM, wn = wid / NWM;
    const int gid  = lane >> 2, tig = lane & 3;
    const int m0   = blockIdx.y * BM, n0 = blockIdx.x * 128;

    const int lrow = tid >> 3;
    const int lc4  = (tid & 7) * 4;

    uint32_t As_base = (uint32_t)__cvta_generic_to_shared(As);
    uint32_t Ws_base = (uint32_t)__cvta_generic_to_shared(Ws);

    const int rowA_in  = (lane & 15);
    const int koffA    = ((lane >> 4) & 1) * 4;
    const int rowB_in  = (lane & 7) + (((lane >> 4) & 1) << 3);
    const int koffB    = ((lane >> 3) & 1) * 4;

    float acc[2][NT][4] = {};
    const int ktiles = K >> 5;

    auto load_tile = [&](int kt, int buf) {
        const float* Ag = A + (size_t)m0 * K + kt * 32;
        #pragma unroll
        for (int i = 0; i < BM / 32; i++) {
            int row = lrow + i * 32;
            uint32_t s = As_base + (buf * ASTG + swz(row, lc4)) * 4;
            cp16(s, Ag + (size_t)row * K + lc4, (m0 + row) < M);
        }
        const float* Wg = W + (size_t)n0 * K + kt * 32;
        #pragma unroll
        for (int i = 0; i < 4; i++) {
            int row = lrow + i * 32;
            uint32_t s = Ws_base + (buf * 4096 + swz(row, lc4)) * 4;
            cp16(s, Wg + (size_t)row * K + lc4, true);
        }
    };

    load_tile(0, 0);
    cp_commit();
    if (ktiles > 1) { load_tile(1, 1); cp_commit(); }

    for (int kt = 0; kt < ktiles; kt++) {
        if (kt + 2 < ktiles) {
            load_tile(kt + 2, (kt + 2) % 3);
            cp_commit();
            cp_wait<2>();
        } else if (kt + 1 < ktiles) {
            cp_wait<1>();
        } else {
            cp_wait<0>();
        }
        __syncthreads();

        const uint32_t as_b = As_base + ((kt % 3) * ASTG) * 4;
        const uint32_t ws_b = Ws_base + ((kt % 3) * 4096) * 4;
        #pragma unroll
        for (int ks = 0; ks < 32; ks += 8) {
            uint32_t af[2][4];
            #pragma unroll
            for (int mt = 0; mt < 2; mt++) {
                int row = wm * 32 + mt * 16 + rowA_in;
                int col = ks + koffA;
                uint32_t addr = as_b + (uint32_t)swz(row, col) * 4;
                ldsm4(addr, af[mt][0], af[mt][1], af[mt][2], af[mt][3]);
            }
            #pragma unroll
            for (int np = 0; np < NP; np++) {
                int row = wn * WN + np * 16 + rowB_in;
                int col = ks + koffB;
                uint32_t addr = ws_b + (uint32_t)swz(row, col) * 4;
                uint32_t b0a, b1a, b0b, b1b;
                ldsm4(addr, b0a, b1a, b0b, b1b);
                mma_tf32(acc[0][2 * np    ], af[0], b0a, b1a);
                mma_tf32(acc[1][2 * np    ], af[1], b0a, b1a);
                mma_tf32(acc[0][2 * np + 1], af[0], b0b, b1b);
                mma_tf32(acc[1][2 * np + 1], af[1], b0b, b1b);
            }
        }
        __syncthreads();
    }

    #pragma unroll
    for (int mt = 0; mt < 2; mt++) {
        #pragma unroll
        for (int half = 0; half < 2; half++) {
            int m = m0 + wm * 32 + mt * 16 + gid + half * 8;
            if (m >= M) continue;
            int mres = POSMOD ? (m % NTOK) : m;
            #pragma unroll
            for (int nt = 0; nt < NT; nt++) {
                int n = n0 + wn * WN + nt * 8 + tig * 2;
                float v0 = acc[mt][nt][half * 2 + 0];
                float v1 = acc[mt][nt][half * 2 + 1];
                if (HASBIAS) { v0 += bias[n]; v1 += bias[n + 1]; }
                if (ACT == 1) { v0 = gelu_exact(v0); v1 = gelu_exact(v1); }
                if (HASRES) {
                    float2 r = *(const float2*)&res[(size_t)mres * Nn + n];
                    v0 += r.x; v1 += r.y;
                }
                if (TRUNC) { v0 = ftrunc_tf(v0); v1 = ftrunc_tf(v1); }
                *(float2*)&C[(size_t)m * Nn + n] = make_float2(v0, v1);
            }
        }
    }
}

// ---------------- LayerNorm (warp/token, float4, tf32-truncated out) ------
__global__ void ln_kernel(const float* __restrict__ in, const float* __restrict__ w,
                          const float* __restrict__ b, float* __restrict__ out) {
    int warp = threadIdx.x / 32, lane = threadIdx.x % 32;
    int m = blockIdx.x * 8 + warp;
    if (m >= MTOK) return;
    const float* row = in + (size_t)m * DIM + lane * 8;
    float4 a = *(const float4*)row;
    float4 c = *(const float4*)(row + 4);
    float s  = a.x + a.y + a.z + a.w + c.x + c.y + c.z + c.w;
    float s2 = a.x*a.x + a.y*a.y + a.z*a.z + a.w*a.w
             + c.x*c.x + c.y*c.y + c.z*c.z + c.w*c.w;
    #pragma unroll
    for (int o = 16; o; o >>= 1) {
        s  += __shfl_xor_sync(0xffffffffu, s,  o);
        s2 += __shfl_xor_sync(0xffffffffu, s2, o);
    }
    float mean = s * (1.f / 256.f);
    float var  = s2 * (1.f / 256.f) - mean * mean;
    float rstd = rsqrtf(var + 1e-5f);
    float4 w0 = *(const float4*)(w + lane * 8);
    float4 w1 = *(const float4*)(w + lane * 8 + 4);
    float4 b0 = *(const float4*)(b + lane * 8);
    float4 b1 = *(const float4*)(b + lane * 8 + 4);
    float4 o0, o1;
    o0.x = ftrunc_tf((a.x - mean) * rstd * w0.x + b0.x);
    o0.y = ftrunc_tf((a.y - mean) * rstd * w0.y + b0.y);
    o0.z = ftrunc_tf((a.z - mean) * rstd * w0.z + b0.z);
    o0.w = ftrunc_tf((a.w - mean) * rstd * w0.w + b0.w);
    o1.x = ftrunc_tf((c.x - mean) * rstd * w1.x + b1.x);
    o1.y = ftrunc_tf((c.y - mean) * rstd * w1.y + b1.y);
    o1.z = ftrunc_tf((c.z - mean) * rstd * w1.z + b1.z);
    o1.w = ftrunc_tf((c.w - mean) * rstd * w1.w + b1.w);
    float* orow = out + (size_t)m * DIM + lane * 8;
    *(float4*)orow = o0;
    *(float4*)(orow + 4) = o1;
}

// ---------------- MMA flash attention, q-tile 128, 8 warps ----------------
__global__ void __launch_bounds__(256)
attn_mma(const float* __restrict__ scale_d) {
    __shared__ uint32_t Ks[32 * 36];
    __shared__ uint32_t Vs[32 * 40];
    __shared__ uint32_t Ps[8][16 * 36];

    const int bh = blockIdx.y;
    const int b = bh >> 3, h = bh & 7;
    const int tid = threadIdx.x;
    const int warp = tid >> 5, lane = tid & 31;
    const int gid = lane >> 2, tig = lane & 3;
    const int q0 = (gridDim.x - 1 - blockIdx.x) * 128;  // longest blocks first
    const float* base = g_qkv + (size_t)b * NTOK * 768;
    const float sc = scale_d[h];

    const int i0 = q0 + warp * 16 + gid;
    const int i1 = i0 + 8;

    uint32_t qf[4][4];
    #pragma unroll
    for (int ks = 0; ks < 4; ks++) {
        int c = h * 32 + ks * 8 + tig;
        float v00 = 0.f, v10 = 0.f, v01 = 0.f, v11 = 0.f;
        if (i0 < NTOK) { v00 = base[(size_t)i0 * 768 + c] * sc;
                         v01 = base[(size_t)i0 * 768 + c + 4] * sc; }
        if (i1 < NTOK) { v10 = base[(size_t)i1 * 768 + c] * sc;
                         v11 = base[(size_t)i1 * 768 + c + 4] * sc; }
        qf[ks][0] = f2tf(v00); qf[ks][1] = f2tf(v10);
        qf[ks][2] = f2tf(v01); qf[ks][3] = f2tf(v11);
    }

    float m0 = -1e30f, m1 = -1e30f, l0 = 0.f, l1 = 0.f;
    float oacc[4][4] = {};

    const int jmax = min(q0 + 127, NTOK - 1);
    for (int j0 = 0; j0 < jmax; j0 += 32) {
        __syncthreads();
        {
            int r  = tid >> 3;
            int c4 = (tid & 7) * 4;
            int j  = j0 + r;
            if (j < NTOK) {
                const float* kp = base + (size_t)j * 768 + 256 + h * 32 + c4;
                const float* vp = base + (size_t)j * 768 + 512 + h * 32 + c4;
                float4 ka = *(const float4*)kp;
                Ks[r * 36 + c4 + 0] = f2tf(ka.x); Ks[r * 36 + c4 + 1] = f2tf(ka.y);
                Ks[r * 36 + c4 + 2] = f2tf(ka.z); Ks[r * 36 + c4 + 3] = f2tf(ka.w);
                float4 va = *(const float4*)vp;
                Vs[r * 40 + c4 + 0] = f2tf(va.x); Vs[r * 40 + c4 + 1] = f2tf(va.y);
                Vs[r * 40 + c4 + 2] = f2tf(va.z); Vs[r * 40 + c4 + 3] = f2tf(va.w);
            } else {
                #pragma unroll
                for (int q = 0; q < 4; q++) {
                    Ks[r * 36 + c4 + q] = 0;
                    Vs[r * 40 + c4 + q] = 0;
                }
            }
        }
        __syncthreads();

        float s[4][4] = {};
        #pragma unroll
        for (int ks = 0; ks < 4; ks++) {
            #pragma unroll
            for (int nt = 0; nt < 4; nt++) {
                uint32_t b0 = Ks[(nt * 8 + gid) * 36 + ks * 8 + tig];
                uint32_t b1 = Ks[(nt * 8 + gid) * 36 + ks * 8 + tig + 4];
                mma_tf32(s[nt], qf[ks], b0, b1);
            }
        }

        float rm0 = -1e30f, rm1 = -1e30f;
        #pragma unroll
        for (int nt = 0; nt < 4; nt++) {
            int jc = j0 + nt * 8 + tig * 2;
            if (jc     >= i0) s[nt][0] = -1e30f;
            if (jc + 1 >= i0) s[nt][1] = -1e30f;
            if (jc     >= i1) s[nt][2] = -1e30f;
            if (jc + 1 >= i1) s[nt][3] = -1e30f;
            rm0 = fmaxf(rm0, fmaxf(s[nt][0], s[nt][1]));
            rm1 = fmaxf(rm1, fmaxf(s[nt][2], s[nt][3]));
        }
        rm0 = fmaxf(rm0, __shfl_xor_sync(0xffffffffu, rm0, 1));
        rm0 = fmaxf(rm0, __shfl_xor_sync(0xffffffffu, rm0, 2));
        rm1 = fmaxf(rm1, __shfl_xor_sync(0xffffffffu, rm1, 1));
        rm1 = fmaxf(rm1, __shfl_xor_sync(0xffffffffu, rm1, 2));
        float mn0 = fmaxf(m0, rm0), mn1 = fmaxf(m1, rm1);
        float corr0 = __expf(m0 - mn0), corr1 = __expf(m1 - mn1);

        float p[4][4];
        float ps0 = 0.f, ps1 = 0.f;
        #pragma unroll
        for (int nt = 0; nt < 4; nt++) {
            p[nt][0] = (s[nt][0] < -1e29f) ? 0.f : __expf(s[nt][0] - mn0);
            p[nt][1] = (s[nt][1] < -1e29f) ? 0.f : __expf(s[nt][1] - mn0);
            p[nt][2] = (s[nt][2] < -1e29f) ? 0.f : __expf(s[nt][2] - mn1);
            p[nt][3] = (s[nt][3] < -1e29f) ? 0.f : __expf(s[nt][3] - mn1);
            ps0 += p[nt][0] + p[nt][1];
            ps1 += p[nt][2] + p[nt][3];
        }
        ps0 += __shfl_xor_sync(0xffffffffu, ps0, 1);
        ps0 += __shfl_xor_sync(0xffffffffu, ps0, 2);
        ps1 += __shfl_xor_sync(0xffffffffu, ps1, 1);
        ps1 += __shfl_xor_sync(0xffffffffu, ps1, 2);
        l0 = l0 * corr0 + ps0;
        l1 = l1 * corr1 + ps1;
        #pragma unroll
        for (int nt = 0; nt < 4; nt++) {
            oacc[nt][0] *= corr0; oacc[nt][1] *= corr0;
            oacc[nt][2] *= corr1; oacc[nt][3] *= corr1;
        }

        uint32_t* pw = Ps[warp];
        __syncwarp();
        #pragma unroll
        for (int nt = 0; nt < 4; nt++) {
            pw[gid * 36 + nt * 8 + tig * 2    ]  = f2tf(p[nt][0]);
            pw[gid * 36 + nt * 8 + tig * 2 + 1]  = f2tf(p[nt][1]);
            pw[(gid + 8) * 36 + nt * 8 + tig * 2    ] = f2tf(p[nt][2]);
            pw[(gid + 8) * 36 + nt * 8 + tig * 2 + 1] = f2tf(p[nt][3]);
        }
        __syncwarp();

        #pragma unroll
        for (int ks = 0; ks < 4; ks++) {
            uint32_t af[4];
            af[0] = pw[gid * 36 + ks * 8 + tig];
            af[1] = pw[(gid + 8) * 36 + ks * 8 + tig];
            af[2] = pw[gid * 36 + ks * 8 + tig + 4];
            af[3] = pw[(gid + 8) * 36 + ks * 8 + tig + 4];
            #pragma unroll
            for (int nt = 0; nt < 4; nt++) {
                uint32_t b0 = Vs[(ks * 8 + tig) * 40 + nt * 8 + gid];
                uint32_t b1 = Vs[(ks * 8 + tig + 4) * 40 + nt * 8 + gid];
                mma_tf32(oacc[nt], af, b0, b1);
            }
        }
        m0 = mn0; m1 = mn1;
    }

    float inv0 = (l0 > 0.f) ? 1.f / l0 : 0.f;
    float inv1 = (l1 > 0.f) ? 1.f / l1 : 0.f;
    #pragma unroll
    for (int nt = 0; nt < 4; nt++) {
        int col = h * 32 + nt * 8 + tig * 2;
        if (i0 < NTOK) {
            float2 o = make_float2(ftrunc_tf(oacc[nt][0] * inv0),
                                   ftrunc_tf(oacc[nt][1] * inv0));
            *(float2*)&g_attn[((size_t)b * NTOK + i0) * DIM + col] = o;
        }
        if (i1 < NTOK) {
            float2 o = make_float2(ftrunc_tf(oacc[nt][2] * inv1),
                                   ftrunc_tf(oacc[nt][3] * inv1));
            *(float2*)&g_attn[((size_t)b * NTOK + i1) * DIM + col] = o;
        }
    }
}

// ---------------- untokenize + crop ----------------------------------------
__global__ void reshape_kernel(const float* __restrict__ pix, float* __restrict__ out) {
    int idx = blockIdx.x * blockDim.x + threadIdx.x;
    const int total = BATCH * IMGS * IMGS;
    if (idx >= total) return;
    int b   = idx / (IMGS * IMGS);
    int rem = idx % (IMGS * IMGS);
    int y = rem / IMGS, x = rem % IMGS;
    int py = y >> 4, pr = y & 15, px = x >> 4, pc = x & 15;
    int m = b * NTOK + py * HP + px;
    out[idx] = pix[(size_t)m * 256 + pr * 16 + pc];
}

// ---------------- host orchestration ---------------------------------------
static inline dim3 gg(int M, int Nn, int BM) { return dim3(Nn / 128, (M + BM - 1) / BM); }

extern "C" void kernel_launch(void* const* d_in, const int* in_sizes, int n_in,
                              void* d_out, int out_size) {
    const float* x      = (const float*)d_in[0];
    const float* pos    = (const float*)d_in[1];
    const float* spt_w  = (const float*)d_in[2];
    const float* spt_b  = (const float*)d_in[3];
    const float* ln1_w  = (const float*)d_in[4];
    const float* ln1_b  = (const float*)d_in[5];
    const float* scale  = (const float*)d_in[6];
    const float* wqkv   = (const float*)d_in[7];
    const float* wout   = (const float*)d_in[8];
    const float* bout   = (const float*)d_in[9];
    const float* ln2_w  = (const float*)d_in[10];
    const float* ln2_b  = (const float*)d_in[11];
    const float* ff1_w  = (const float*)d_in[12];
    const float* ff1_b  = (const float*)d_in[13];
    const float* ff2_w  = (const float*)d_in[14];
    const float* ff2_b  = (const float*)d_in[15];
    const float* pix_w  = (const float*)d_in[16];
    const float* pix_b  = (const float*)d_in[17];

    float *tok, *t, *ln, *qkv, *attn, *ff, *wtf;
    cudaGetSymbolAddress((void**)&tok,  g_tok);
    cudaGetSymbolAddress((void**)&t,    g_t);
    cudaGetSymbolAddress((void**)&ln,   g_ln);
    cudaGetSymbolAddress((void**)&qkv,  g_qkv);
    cudaGetSymbolAddress((void**)&attn, g_attn);
    cudaGetSymbolAddress((void**)&ff,   g_ff);
    cudaGetSymbolAddress((void**)&wtf,  g_wtf);

    // BM=64 variants (N=256 launches)
    cudaFuncSetAttribute(gemm_tc<64, 0, true,  true,  true,  false>, cudaFuncAttributeMaxDynamicSharedMemorySize, GEMM_SMEM(64));
    cudaFuncSetAttribute(gemm_tc<64, 0, true,  true,  false, false>, cudaFuncAttributeMaxDynamicSharedMemorySize, GEMM_SMEM(64));
    cudaFuncSetAttribute(gemm_tc<64, 0, true,  false, false, false>, cudaFuncAttributeMaxDynamicSharedMemorySize, GEMM_SMEM(64));
    // BM=128 variants (qkv, ff1)
    cudaFuncSetAttribute(gemm_tc<128, 0, false, false, false, false>, cudaFuncAttributeMaxDynamicSharedMemorySize, GEMM_SMEM(128));
    cudaFuncSetAttribute(gemm_tc<128, 1, true,  false, false, true >, cudaFuncAttributeMaxDynamicSharedMemorySize, GEMM_SMEM(128));

    convert_w<<<(W_TOTAL / 4 + 255) / 256, 256>>>(spt_w, wqkv, wout, ff1_w, ff2_w, pix_w);
    {
        int total = MTOK * 1280;
        tokenize_kernel<<<(total + 255) / 256, 256>>>(x);
    }
    gemm_tc<64, 0, true, true, true, false><<<gg(MTOK, DIM, 64), 256, GEMM_SMEM(64)>>>(
        tok, wtf + W_SPT_OFF, spt_b, pos, t, MTOK, DIM, 1280);

    const int LN_BLOCKS = (MTOK + 7) / 8;
    for (int d = 0; d < 3; d++) {
        ln_kernel<<<LN_BLOCKS, 256>>>(t, ln1_w + d * DIM, ln1_b + d * DIM, ln);
        gemm_tc<128, 0, false, false, false, false><<<gg(MTOK, 768, 128), 256, GEMM_SMEM(128)>>>(
            ln, wtf + W_QKV_OFF + (size_t)d * 768 * DIM, nullptr, nullptr, qkv, MTOK, 768, DIM);
        {
            dim3 grid((NTOK + 127) / 128, BATCH * NHEADS);
            attn_mma<<<grid, 256>>>(scale + d * NHEADS);
        }
        gemm_tc<64, 0, true, true, false, false><<<gg(MTOK, DIM, 64), 256, GEMM_SMEM(64)>>>(
            attn, wtf + W_WOUT_OFF + (size_t)d * DIM * DIM, bout + d * DIM, t, t, MTOK, DIM, DIM);
        ln_kernel<<<LN_BLOCKS, 256>>>(t, ln2_w + d * DIM, ln2_b + d * DIM, ln);
        gemm_tc<128, 1, true, false, false, true><<<gg(MTOK, 1024, 128), 256, GEMM_SMEM(128)>>>(
            ln, wtf + W_FF1_OFF + (size_t)d * 1024 * DIM, ff1_b + d * 1024, nullptr, ff, MTOK, 1024, DIM);
        gemm_tc<64, 0, true, true, false, false><<<gg(MTOK, DIM, 64), 256, GEMM_SMEM(64)>>>(
            ff, wtf + W_FF2_OFF + (size_t)d * DIM * 1024, ff2_b + d * DIM, t, t, MTOK, DIM, 1024);
    }

    gemm_tc<64, 0, true, false, false, false><<<gg(MTOK, DIM, 64), 256, GEMM_SMEM(64)>>>(
        t, wtf + W_PIX_OFF, pix_b, nullptr, qkv, MTOK, DIM, DIM);

    {
        int total = BATCH * IMGS * IMGS;
        reshape_kernel<<<(total + 255) / 256, 256>>>(qkv, (float*)d_out);
    }
}

// round 12
// speedup vs baseline: 1.2898x; 1.0321x over previous
#include <cuda_runtime.h>
#include <math.h>
#include <stdint.h>

#define IMGS   457
#define HPAD   464
#define HP     29
#define NTOK   841
#define BATCH  8
#define DIM    256
#define MTOK   (BATCH*NTOK)   // 6728
#define NHEADS 8
#define DH     32

// ---------------- scratch (device globals; no allocations) ----------------
__device__ float g_t   [MTOK*DIM];
__device__ float g_ln  [MTOK*DIM];
__device__ float g_qkv [MTOK*768];
__device__ float g_attn[MTOK*DIM];
__device__ float g_ff  [MTOK*1024];

// pre-truncated (tf32) weights
#define W_SPT_OFF  0
#define W_SPT_SZ   (256*1280)
#define W_QKV_OFF  (W_SPT_OFF+W_SPT_SZ)
#define W_QKV_SZ   (3*768*256)
#define W_WOUT_OFF (W_QKV_OFF+W_QKV_SZ)
#define W_WOUT_SZ  (3*256*256)
#define W_FF1_OFF  (W_WOUT_OFF+W_WOUT_SZ)
#define W_FF1_SZ   (3*1024*256)
#define W_FF2_OFF  (W_FF1_OFF+W_FF1_SZ)
#define W_FF2_SZ   (3*256*1024)
#define W_PIX_OFF  (W_FF2_OFF+W_FF2_SZ)
#define W_PIX_SZ   (256*256)
#define W_TOTAL    (W_PIX_OFF+W_PIX_SZ)
__device__ float g_wtf[W_TOTAL];

__device__ __forceinline__ uint32_t f2tf(float f) {
    uint32_t r;
    asm("cvt.rna.tf32.f32 %0, %1;" : "=r"(r) : "f"(f));
    return r;
}
__device__ __forceinline__ float ftrunc_tf(float f) { return __uint_as_float(f2tf(f)); }

__global__ void convert_w(const float* __restrict__ spt, const float* __restrict__ qkv,
                          const float* __restrict__ wo, const float* __restrict__ f1,
                          const float* __restrict__ f2w, const float* __restrict__ px) {
    int i4 = blockIdx.x * 256 + threadIdx.x;
    if (i4 >= W_TOTAL / 4) return;
    int i = i4 * 4;
    const float* src; int off;
    if      (i < W_QKV_OFF)  { src = spt; off = 0; }
    else if (i < W_WOUT_OFF) { src = qkv; off = W_QKV_OFF; }
    else if (i < W_FF1_OFF)  { src = wo;  off = W_WOUT_OFF; }
    else if (i < W_FF2_OFF)  { src = f1;  off = W_FF1_OFF; }
    else if (i < W_PIX_OFF)  { src = f2w; off = W_FF2_OFF; }
    else                     { src = px;  off = W_PIX_OFF; }
    float4 v = *(const float4*)(src + (i - off));
    v.x = ftrunc_tf(v.x); v.y = ftrunc_tf(v.y);
    v.z = ftrunc_tf(v.z); v.w = ftrunc_tf(v.w);
    *(float4*)&g_wtf[i] = v;
}

// ---------------- tf32 tensor-core GEMM, 3-stage cp.async, LDSM frags -----
// Template BM in {64,128}; BN=128 fixed; 256 threads.
// GATHER: A is the raw image [8,457,457]; loader performs pad+roll+patchify
//         via 4-byte cp.async (image rows are only 4B aligned!).
// RESHAPE: C is the output image; epilogue performs untokenize+crop.
__device__ __forceinline__ void mma_tf32(float c[4], const uint32_t a[4],
                                         uint32_t b0, uint32_t b1) {
    asm volatile(
        "mma.sync.aligned.m16n8k8.row.col.f32.tf32.tf32.f32 "
        "{%0,%1,%2,%3}, {%4,%5,%6,%7}, {%8,%9}, {%0,%1,%2,%3};"
        : "+f"(c[0]), "+f"(c[1]), "+f"(c[2]), "+f"(c[3])
        : "r"(a[0]), "r"(a[1]), "r"(a[2]), "r"(a[3]), "r"(b0), "r"(b1));
}
__device__ __forceinline__ float gelu_exact(float v) {
    return 0.5f * v * (1.0f + erff(v * 0.70710678118654752440f));
}
__device__ __forceinline__ void cp16(uint32_t saddr, const float* g, bool pred) {
    asm volatile("cp.async.cg.shared.global [%0], [%1], 16, %2;"
                 :: "r"(saddr), "l"(g), "r"(pred ? 16 : 0));
}
__device__ __forceinline__ void cp4(uint32_t saddr, const float* g, bool pred) {
    asm volatile("cp.async.ca.shared.global [%0], [%1], 4, %2;"
                 :: "r"(saddr), "l"(g), "r"(pred ? 4 : 0));
}
__device__ __forceinline__ void cp_commit() { asm volatile("cp.async.commit_group;"); }
template<int N>
__device__ __forceinline__ void cp_wait() {
    asm volatile("cp.async.wait_group %0;" :: "n"(N));
}
__device__ __forceinline__ int swz(int row, int col) {
    return row * 32 + (col ^ ((row & 7) * 4));
}
__device__ __forceinline__ void ldsm4(uint32_t addr, uint32_t& r0, uint32_t& r1,
                                      uint32_t& r2, uint32_t& r3) {
    asm volatile("ldmatrix.sync.aligned.m8n8.x4.shared.b16 {%0,%1,%2,%3}, [%4];"
                 : "=r"(r0), "=r"(r1), "=r"(r2), "=r"(r3) : "r"(addr));
}

#define GEMM_SMEM(BM) (3 * ((BM) * 32 + 4096) * 4)

template<int BM, int ACT, bool HASBIAS, bool HASRES, bool POSMOD, bool TRUNC,
         bool GATHER, bool RESHAPE>
__global__ void __launch_bounds__(256)
gemm_tc(const float* __restrict__ A, const float* __restrict__ W,
        const float* __restrict__ bias, const float* __restrict__ res,
        float* __restrict__ C, int M, int Nn, int K) {
    constexpr int NWM = BM / 32;
    constexpr int NWN = 8 / NWM;
    constexpr int WN  = 128 / NWN;
    constexpr int NP  = WN / 16;
    constexpr int NT  = WN / 8;
    constexpr int ASTG = BM * 32;

    extern __shared__ float smem[];
    float* As = smem;
    float* Ws = smem + 3 * ASTG;
    const int tid  = threadIdx.x;
    const int wid  = tid >> 5, lane = tid & 31;
    const int wm   = wid % NWM, wn = wid / NWM;
    const int gid  = lane >> 2, tig = lane & 3;
    const int m0   = blockIdx.y * BM, n0 = blockIdx.x * 128;

    const int lrow = tid >> 3;
    const int lc4  = (tid & 7) * 4;

    uint32_t As_base = (uint32_t)__cvta_generic_to_shared(As);
    uint32_t Ws_base = (uint32_t)__cvta_generic_to_shared(Ws);

    const int rowA_in  = (lane & 15);
    const int koffA    = ((lane >> 4) & 1) * 4;
    const int rowB_in  = (lane & 7) + (((lane >> 4) & 1) << 3);
    const int koffB    = ((lane >> 3) & 1) * 4;

    // per-row gather precompute (token -> batch / patch coords)
    bool grow[BM / 32];
    int  gb[BM / 32], gpy[BM / 32], gpx[BM / 32];
    if (GATHER) {
        #pragma unroll
        for (int i = 0; i < BM / 32; i++) {
            int m = m0 + lrow + i * 32;
            grow[i] = m < M;
            int mm = m < M ? m : (M - 1);
            gb[i] = mm / NTOK;
            int n8 = mm - gb[i] * NTOK;
            gpy[i] = n8 / HP;
            gpx[i] = n8 - gpy[i] * HP;
        }
    }

    float acc[2][NT][4] = {};
    const int ktiles = K >> 5;

    auto load_tile = [&](int kt, int buf) {
        if (GATHER) {
            int c  = kt * 32 + lc4;
            int s  = c >> 8;
            int pr = (c >> 4) & 15;
            int pc = c & 15;
            int dy = (s == 0) ? 0 : ((s <= 2) ? -8 : 8);
            int dx = (s == 0) ? 0 : ((s & 1) ? -8 : 8);
            #pragma unroll
            for (int i = 0; i < BM / 32; i++) {
                int row = lrow + i * 32;
                uint32_t sdst = As_base + (buf * ASTG + swz(row, lc4)) * 4;
                int y  = gpy[i] * 16 + pr - dy;
                if (y < 0) y += HPAD; if (y >= HPAD) y -= HPAD;
                int xx = gpx[i] * 16 + pc - dx;
                if (xx < 0) xx += HPAD; if (xx >= HPAD) xx -= HPAD;
                bool yv = grow[i] && (y < IMGS);
                const float* src = A + ((size_t)gb[i] * IMGS + y) * IMGS + xx;
                // image rows are 4B-aligned only -> element-wise cp.async
                #pragma unroll
                for (int q = 0; q < 4; q++)
                    cp4(sdst + q * 4, src + q, yv && (xx + q) < IMGS);
            }
        } else {
            const float* Ag = A + (size_t)m0 * K + kt * 32;
            #pragma unroll
            for (int i = 0; i < BM / 32; i++) {
                int row = lrow + i * 32;
                uint32_t s = As_base + (buf * ASTG + swz(row, lc4)) * 4;
                cp16(s, Ag + (size_t)row * K + lc4, (m0 + row) < M);
            }
        }
        const float* Wg = W + (size_t)n0 * K + kt * 32;
        #pragma unroll
        for (int i = 0; i < 4; i++) {
            int row = lrow + i * 32;
            uint32_t s = Ws_base + (buf * 4096 + swz(row, lc4)) * 4;
            cp16(s, Wg + (size_t)row * K + lc4, true);
        }
    };

    load_tile(0, 0);
    cp_commit();
    if (ktiles > 1) { load_tile(1, 1); cp_commit(); }

    for (int kt = 0; kt < ktiles; kt++) {
        if (kt + 2 < ktiles) {
            load_tile(kt + 2, (kt + 2) % 3);
            cp_commit();
            cp_wait<2>();
        } else if (kt + 1 < ktiles) {
            cp_wait<1>();
        } else {
            cp_wait<0>();
        }
        __syncthreads();

        const uint32_t as_b = As_base + ((kt % 3) * ASTG) * 4;
        const uint32_t ws_b = Ws_base + ((kt % 3) * 4096) * 4;
        #pragma unroll
        for (int ks = 0; ks < 32; ks += 8) {
            uint32_t af[2][4];
            #pragma unroll
            for (int mt = 0; mt < 2; mt++) {
                int row = wm * 32 + mt * 16 + rowA_in;
                int col = ks + koffA;
                uint32_t addr = as_b + (uint32_t)swz(row, col) * 4;
                ldsm4(addr, af[mt][0], af[mt][1], af[mt][2], af[mt][3]);
            }
            #pragma unroll
            for (int np = 0; np < NP; np++) {
                int row = wn * WN + np * 16 + rowB_in;
                int col = ks + koffB;
                uint32_t addr = ws_b + (uint32_t)swz(row, col) * 4;
                uint32_t b0a, b1a, b0b, b1b;
                ldsm4(addr, b0a, b1a, b0b, b1b);
                mma_tf32(acc[0][2 * np    ], af[0], b0a, b1a);
                mma_tf32(acc[1][2 * np    ], af[1], b0a, b1a);
                mma_tf32(acc[0][2 * np + 1], af[0], b0b, b1b);
                mma_tf32(acc[1][2 * np + 1], af[1], b0b, b1b);
            }
        }
        __syncthreads();
    }

    #pragma unroll
    for (int mt = 0; mt < 2; mt++) {
        #pragma unroll
        for (int half = 0; half < 2; half++) {
            int m = m0 + wm * 32 + mt * 16 + gid + half * 8;
            if (m >= M) continue;
            int mres = POSMOD ? (m % NTOK) : m;
            int ob = 0, opy = 0, opx = 0;
            if (RESHAPE) {
                ob = m / NTOK;
                int n8 = m - ob * NTOK;
                opy = n8 / HP;
                opx = n8 - opy * HP;
            }
            #pragma unroll
            for (int nt = 0; nt < NT; nt++) {
                int n = n0 + wn * WN + nt * 8 + tig * 2;
                float v0 = acc[mt][nt][half * 2 + 0];
                float v1 = acc[mt][nt][half * 2 + 1];
                if (HASBIAS) { v0 += bias[n]; v1 += bias[n + 1]; }
                if (ACT == 1) { v0 = gelu_exact(v0); v1 = gelu_exact(v1); }
                if (HASRES) {
                    float2 r = *(const float2*)&res[(size_t)mres * Nn + n];
                    v0 += r.x; v1 += r.y;
                }
                if (TRUNC) { v0 = ftrunc_tf(v0); v1 = ftrunc_tf(v1); }
                if (RESHAPE) {
                    int y  = opy * 16 + (n >> 4);
                    int xc = opx * 16 + (n & 15);
                    if (y < IMGS) {
                        float* orow = C + ((size_t)ob * IMGS + y) * IMGS;
                        if (xc < IMGS)     orow[xc]     = v0;
                        if (xc + 1 < IMGS) orow[xc + 1] = v1;
                    }
                } else {
                    *(float2*)&C[(size_t)m * Nn + n] = make_float2(v0, v1);
                }
            }
        }
    }
}

// ---------------- LayerNorm (warp/token, float4, tf32-truncated out) ------
__global__ void ln_kernel(const float* __restrict__ in, const float* __restrict__ w,
                          const float* __restrict__ b, float* __restrict__ out) {
    int warp = threadIdx.x / 32, lane = threadIdx.x % 32;
    int m = blockIdx.x * 8 + warp;
    if (m >= MTOK) return;
    const float* row = in + (size_t)m * DIM + lane * 8;
    float4 a = *(const float4*)row;
    float4 c = *(const float4*)(row + 4);
    float s  = a.x + a.y + a.z + a.w + c.x + c.y + c.z + c.w;
    float s2 = a.x*a.x + a.y*a.y + a.z*a.z + a.w*a.w
             + c.x*c.x + c.y*c.y + c.z*c.z + c.w*c.w;
    #pragma unroll
    for (int o = 16; o; o >>= 1) {
        s  += __shfl_xor_sync(0xffffffffu, s,  o);
        s2 += __shfl_xor_sync(0xffffffffu, s2, o);
    }
    float mean = s * (1.f / 256.f);
    float var  = s2 * (1.f / 256.f) - mean * mean;
    float rstd = rsqrtf(var + 1e-5f);
    float4 w0 = *(const float4*)(w + lane * 8);
    float4 w1 = *(const float4*)(w + lane * 8 + 4);
    float4 b0 = *(const float4*)(b + lane * 8);
    float4 b1 = *(const float4*)(b + lane * 8 + 4);
    float4 o0, o1;
    o0.x = ftrunc_tf((a.x - mean) * rstd * w0.x + b0.x);
    o0.y = ftrunc_tf((a.y - mean) * rstd * w0.y + b0.y);
    o0.z = ftrunc_tf((a.z - mean) * rstd * w0.z + b0.z);
    o0.w = ftrunc_tf((a.w - mean) * rstd * w0.w + b0.w);
    o1.x = ftrunc_tf((c.x - mean) * rstd * w1.x + b1.x);
    o1.y = ftrunc_tf((c.y - mean) * rstd * w1.y + b1.y);
    o1.z = ftrunc_tf((c.z - mean) * rstd * w1.z + b1.z);
    o1.w = ftrunc_tf((c.w - mean) * rstd * w1.w + b1.w);
    float* orow = out + (size_t)m * DIM + lane * 8;
    *(float4*)orow = o0;
    *(float4*)(orow + 4) = o1;
}

// ---------------- MMA flash attention, q-tile 128, 8 warps ----------------
__global__ void __launch_bounds__(256)
attn_mma(const float* __restrict__ scale_d) {
    __shared__ uint32_t Ks[32 * 36];
    __shared__ uint32_t Vs[32 * 40];
    __shared__ uint32_t Ps[8][16 * 36];

    const int bh = blockIdx.y;
    const int b = bh >> 3, h = bh & 7;
    const int tid = threadIdx.x;
    const int warp = tid >> 5, lane = tid & 31;
    const int gid = lane >> 2, tig = lane & 3;
    const int q0 = (gridDim.x - 1 - blockIdx.x) * 128;  // longest blocks first
    const float* base = g_qkv + (size_t)b * NTOK * 768;
    const float sc = scale_d[h];

    const int i0 = q0 + warp * 16 + gid;
    const int i1 = i0 + 8;

    uint32_t qf[4][4];
    #pragma unroll
    for (int ks = 0; ks < 4; ks++) {
        int c = h * 32 + ks * 8 + tig;
        float v00 = 0.f, v10 = 0.f, v01 = 0.f, v11 = 0.f;
        if (i0 < NTOK) { v00 = base[(size_t)i0 * 768 + c] * sc;
                         v01 = base[(size_t)i0 * 768 + c + 4] * sc; }
        if (i1 < NTOK) { v10 = base[(size_t)i1 * 768 + c] * sc;
                         v11 = base[(size_t)i1 * 768 + c + 4] * sc; }
        qf[ks][0] = f2tf(v00); qf[ks][1] = f2tf(v10);
        qf[ks][2] = f2tf(v01); qf[ks][3] = f2tf(v11);
    }

    float m0 = -1e30f, m1 = -1e30f, l0 = 0.f, l1 = 0.f;
    float oacc[4][4] = {};

    const int jmax = min(q0 + 127, NTOK - 1);
    for (int j0 = 0; j0 < jmax; j0 += 32) {
        __syncthreads();
        {
            int r  = tid >> 3;
            int c4 = (tid & 7) * 4;
            int j  = j0 + r;
            if (j < NTOK) {
                const float* kp = base + (size_t)j * 768 + 256 + h * 32 + c4;
                const float* vp = base + (size_t)j * 768 + 512 + h * 32 + c4;
                float4 ka = *(const float4*)kp;
                Ks[r * 36 + c4 + 0] = f2tf(ka.x); Ks[r * 36 + c4 + 1] = f2tf(ka.y);
                Ks[r * 36 + c4 + 2] = f2tf(ka.z); Ks[r * 36 + c4 + 3] = f2tf(ka.w);
                float4 va = *(const float4*)vp;
                Vs[r * 40 + c4 + 0] = f2tf(va.x); Vs[r * 40 + c4 + 1] = f2tf(va.y);
                Vs[r * 40 + c4 + 2] = f2tf(va.z); Vs[r * 40 + c4 + 3] = f2tf(va.w);
            } else {
                #pragma unroll
                for (int q = 0; q < 4; q++) {
                    Ks[r * 36 + c4 + q] = 0;
                    Vs[r * 40 + c4 + q] = 0;
                }
            }
        }
        __syncthreads();

        float s[4][4] = {};
        #pragma unroll
        for (int ks = 0; ks < 4; ks++) {
            #pragma unroll
            for (int nt = 0; nt < 4; nt++) {
                uint32_t b0 = Ks[(nt * 8 + gid) * 36 + ks * 8 + tig];
                uint32_t b1 = Ks[(nt * 8 + gid) * 36 + ks * 8 + tig + 4];
                mma_tf32(s[nt], qf[ks], b0, b1);
            }
        }

        float rm0 = -1e30f, rm1 = -1e30f;
        #pragma unroll
        for (int nt = 0; nt < 4; nt++) {
            int jc = j0 + nt * 8 + tig * 2;
            if (jc     >= i0) s[nt][0] = -1e30f;
            if (jc + 1 >= i0) s[nt][1] = -1e30f;
            if (jc     >= i1) s[nt][2] = -1e30f;
            if (jc + 1 >= i1) s[nt][3] = -1e30f;
            rm0 = fmaxf(rm0, fmaxf(s[nt][0], s[nt][1]));
            rm1 = fmaxf(rm1, fmaxf(s[nt][2], s[nt][3]));
        }
        rm0 = fmaxf(rm0, __shfl_xor_sync(0xffffffffu, rm0, 1));
        rm0 = fmaxf(rm0, __shfl_xor_sync(0xffffffffu, rm0, 2));
        rm1 = fmaxf(rm1, __shfl_xor_sync(0xffffffffu, rm1, 1));
        rm1 = fmaxf(rm1, __shfl_xor_sync(0xffffffffu, rm1, 2));
        float mn0 = fmaxf(m0, rm0), mn1 = fmaxf(m1, rm1);
        float corr0 = __expf(m0 - mn0), corr1 = __expf(m1 - mn1);

        float p[4][4];
        float ps0 = 0.f, ps1 = 0.f;
        #pragma unroll
        for (int nt = 0; nt < 4; nt++) {
            p[nt][0] = (s[nt][0] < -1e29f) ? 0.f : __expf(s[nt][0] - mn0);
            p[nt][1] = (s[nt][1] < -1e29f) ? 0.f : __expf(s[nt][1] - mn0);
            p[nt][2] = (s[nt][2] < -1e29f) ? 0.f : __expf(s[nt][2] - mn1);
            p[nt][3] = (s[nt][3] < -1e29f) ? 0.f : __expf(s[nt][3] - mn1);
            ps0 += p[nt][0] + p[nt][1];
            ps1 += p[nt][2] + p[nt][3];
        }
        ps0 += __shfl_xor_sync(0xffffffffu, ps0, 1);
        ps0 += __shfl_xor_sync(0xffffffffu, ps0, 2);
        ps1 += __shfl_xor_sync(0xffffffffu, ps1, 1);
        ps1 += __shfl_xor_sync(0xffffffffu, ps1, 2);
        l0 = l0 * corr0 + ps0;
        l1 = l1 * corr1 + ps1;
        #pragma unroll
        for (int nt = 0; nt < 4; nt++) {
            oacc[nt][0] *= corr0; oacc[nt][1] *= corr0;
            oacc[nt][2] *= corr1; oacc[nt][3] *= corr1;
        }

        uint32_t* pw = Ps[warp];
        __syncwarp();
        #pragma unroll
        for (int nt = 0; nt < 4; nt++) {
            pw[gid * 36 + nt * 8 + tig * 2    ]  = f2tf(p[nt][0]);
            pw[gid * 36 + nt * 8 + tig * 2 + 1]  = f2tf(p[nt][1]);
            pw[(gid + 8) * 36 + nt * 8 + tig * 2    ] = f2tf(p[nt][2]);
            pw[(gid + 8) * 36 + nt * 8 + tig * 2 + 1] = f2tf(p[nt][3]);
        }
        __syncwarp();

        #pragma unroll
        for (int ks = 0; ks < 4; ks++) {
            uint32_t af[4];
            af[0] = pw[gid * 36 + ks * 8 + tig];
            af[1] = pw[(gid + 8) * 36 + ks * 8 + tig];
            af[2] = pw[gid * 36 + ks * 8 + tig + 4];
            af[3] = pw[(gid + 8) * 36 + ks * 8 + tig + 4];
            #pragma unroll
            for (int nt = 0; nt < 4; nt++) {
                uint32_t b0 = Vs[(ks * 8 + tig) * 40 + nt * 8 + gid];
                uint32_t b1 = Vs[(ks * 8 + tig + 4) * 40 + nt * 8 + gid];
                mma_tf32(oacc[nt], af, b0, b1);
            }
        }
        m0 = mn0; m1 = mn1;
    }

    float inv0 = (l0 > 0.f) ? 1.f / l0 : 0.f;
    float inv1 = (l1 > 0.f) ? 1.f / l1 : 0.f;
    #pragma unroll
    for (int nt = 0; nt < 4; nt++) {
        int col = h * 32 + nt * 8 + tig * 2;
        if (i0 < NTOK) {
            float2 o = make_float2(ftrunc_tf(oacc[nt][0] * inv0),
                                   ftrunc_tf(oacc[nt][1] * inv0));
            *(float2*)&g_attn[((size_t)b * NTOK + i0) * DIM + col] = o;
        }
        if (i1 < NTOK) {
            float2 o = make_float2(ftrunc_tf(oacc[nt][2] * inv1),
                                   ftrunc_tf(oacc[nt][3] * inv1));
            *(float2*)&g_attn[((size_t)b * NTOK + i1) * DIM + col] = o;
        }
    }
}

// ---------------- host orchestration ---------------------------------------
static inline dim3 gg(int M, int Nn, int BM) { return dim3(Nn / 128, (M + BM - 1) / BM); }

extern "C" void kernel_launch(void* const* d_in, const int* in_sizes, int n_in,
                              void* d_out, int out_size) {
    const float* x      = (const float*)d_in[0];
    const float* pos    = (const float*)d_in[1];
    const float* spt_w  = (const float*)d_in[2];
    const float* spt_b  = (const float*)d_in[3];
    const float* ln1_w  = (const float*)d_in[4];
    const float* ln1_b  = (const float*)d_in[5];
    const float* scale  = (const float*)d_in[6];
    const float* wqkv   = (const float*)d_in[7];
    const float* wout   = (const float*)d_in[8];
    const float* bout   = (const float*)d_in[9];
    const float* ln2_w  = (const float*)d_in[10];
    const float* ln2_b  = (const float*)d_in[11];
    const float* ff1_w  = (const float*)d_in[12];
    const float* ff1_b  = (const float*)d_in[13];
    const float* ff2_w  = (const float*)d_in[14];
    const float* ff2_b  = (const float*)d_in[15];
    const float* pix_w  = (const float*)d_in[16];
    const float* pix_b  = (const float*)d_in[17];

    float *t, *ln, *qkv, *attn, *ff, *wtf;
    cudaGetSymbolAddress((void**)&t,    g_t);
    cudaGetSymbolAddress((void**)&ln,   g_ln);
    cudaGetSymbolAddress((void**)&qkv,  g_qkv);
    cudaGetSymbolAddress((void**)&attn, g_attn);
    cudaGetSymbolAddress((void**)&ff,   g_ff);
    cudaGetSymbolAddress((void**)&wtf,  g_wtf);

    cudaFuncSetAttribute(gemm_tc<64, 0, true,  true,  true,  false, true,  false>, cudaFuncAttributeMaxDynamicSharedMemorySize, GEMM_SMEM(64));
    cudaFuncSetAttribute(gemm_tc<64, 0, true,  true,  false, false, false, false>, cudaFuncAttributeMaxDynamicSharedMemorySize, GEMM_SMEM(64));
    cudaFuncSetAttribute(gemm_tc<64, 0, true,  false, false, false, false, true >, cudaFuncAttributeMaxDynamicSharedMemorySize, GEMM_SMEM(64));
    cudaFuncSetAttribute(gemm_tc<128, 0, false, false, false, false, false, false>, cudaFuncAttributeMaxDynamicSharedMemorySize, GEMM_SMEM(128));
    cudaFuncSetAttribute(gemm_tc<128, 1, true,  false, false, true,  false, false>, cudaFuncAttributeMaxDynamicSharedMemorySize, GEMM_SMEM(128));

    convert_w<<<(W_TOTAL / 4 + 255) / 256, 256>>>(spt_w, wqkv, wout, ff1_w, ff2_w, pix_w);

    // spt projection with fused tokenize gather + pos residual
    gemm_tc<64, 0, true, true, true, false, true, false><<<gg(MTOK, DIM, 64), 256, GEMM_SMEM(64)>>>(
        x, wtf + W_SPT_OFF, spt_b, pos, t, MTOK, DIM, 1280);

    const int LN_BLOCKS = (MTOK + 7) / 8;
    for (int d = 0; d < 3; d++) {
        ln_kernel<<<LN_BLOCKS, 256>>>(t, ln1_w + d * DIM, ln1_b + d * DIM, ln);
        gemm_tc<128, 0, false, false, false, false, false, false><<<gg(MTOK, 768, 128), 256, GEMM_SMEM(128)>>>(
            ln, wtf + W_QKV_OFF + (size_t)d * 768 * DIM, nullptr, nullptr, qkv, MTOK, 768, DIM);
        {
            dim3 grid((NTOK + 127) / 128, BATCH * NHEADS);
            attn_mma<<<grid, 256>>>(scale + d * NHEADS);
        }
        gemm_tc<64, 0, true, true, false, false, false, false><<<gg(MTOK, DIM, 64), 256, GEMM_SMEM(64)>>>(
            attn, wtf + W_WOUT_OFF + (size_t)d * DIM * DIM, bout + d * DIM, t, t, MTOK, DIM, DIM);
        ln_kernel<<<LN_BLOCKS, 256>>>(t, ln2_w + d * DIM, ln2_b + d * DIM, ln);
        gemm_tc<128, 1, true, false, false, true, false, false><<<gg(MTOK, 1024, 128), 256, GEMM_SMEM(128)>>>(
            ln, wtf + W_FF1_OFF + (size_t)d * 1024 * DIM, ff1_b + d * 1024, nullptr, ff, MTOK, 1024, DIM);
        gemm_tc<64, 0, true, true, false, false, false, false><<<gg(MTOK, DIM, 64), 256, GEMM_SMEM(64)>>>(
            ff, wtf + W_FF2_OFF + (size_t)d * DIM * 1024, ff2_b + d * DIM, t, t, MTOK, DIM, 1024);
    }

    // pix projection with fused untokenize + crop (writes d_out directly)
    gemm_tc<64, 0, true, false, false, false, false, true><<<gg(MTOK, DIM, 64), 256, GEMM_SMEM(64)>>>(
        t, wtf + W_PIX_OFF, pix_b, nullptr, (float*)d_out, MTOK, DIM, DIM);
}

// round 13
// speedup vs baseline: 1.2932x; 1.0027x over previous
#include <cuda_runtime.h>
#include <math.h>
#include <stdint.h>

#define IMGS   457
#define HPAD   464
#define HP     29
#define NTOK   841
#define BATCH  8
#define DIM    256
#define MTOK   (BATCH*NTOK)   // 6728
#define NHEADS 8
#define DH     32

// ---------------- scratch (device globals; no allocations) ----------------
__device__ float g_t   [MTOK*DIM];
__device__ float g_ln  [MTOK*DIM];
__device__ float g_qkv [MTOK*768];
__device__ float g_attn[MTOK*DIM];
__device__ float g_ff  [MTOK*1024];

// pre-truncated (tf32) weights
#define W_SPT_OFF  0
#define W_SPT_SZ   (256*1280)
#define W_QKV_OFF  (W_SPT_OFF+W_SPT_SZ)
#define W_QKV_SZ   (3*768*256)
#define W_WOUT_OFF (W_QKV_OFF+W_QKV_SZ)
#define W_WOUT_SZ  (3*256*256)
#define W_FF1_OFF  (W_WOUT_OFF+W_WOUT_SZ)
#define W_FF1_SZ   (3*1024*256)
#define W_FF2_OFF  (W_FF1_OFF+W_FF1_SZ)
#define W_FF2_SZ   (3*256*1024)
#define W_PIX_OFF  (W_FF2_OFF+W_FF2_SZ)
#define W_PIX_SZ   (256*256)
#define W_TOTAL    (W_PIX_OFF+W_PIX_SZ)
__device__ float g_wtf[W_TOTAL];

__device__ __forceinline__ uint32_t f2tf(float f) {
    uint32_t r;
    asm("cvt.rna.tf32.f32 %0, %1;" : "=r"(r) : "f"(f));
    return r;
}
__device__ __forceinline__ float ftrunc_tf(float f) { return __uint_as_float(f2tf(f)); }

__global__ void convert_w(const float* __restrict__ spt, const float* __restrict__ qkv,
                          const float* __restrict__ wo, const float* __restrict__ f1,
                          const float* __restrict__ f2w, const float* __restrict__ px) {
    int i4 = blockIdx.x * 256 + threadIdx.x;
    if (i4 >= W_TOTAL / 4) return;
    int i = i4 * 4;
    const float* src; int off;
    if      (i < W_QKV_OFF)  { src = spt; off = 0; }
    else if (i < W_WOUT_OFF) { src = qkv; off = W_QKV_OFF; }
    else if (i < W_FF1_OFF)  { src = wo;  off = W_WOUT_OFF; }
    else if (i < W_FF2_OFF)  { src = f1;  off = W_FF1_OFF; }
    else if (i < W_PIX_OFF)  { src = f2w; off = W_FF2_OFF; }
    else                     { src = px;  off = W_PIX_OFF; }
    float4 v = *(const float4*)(src + (i - off));
    v.x = ftrunc_tf(v.x); v.y = ftrunc_tf(v.y);
    v.z = ftrunc_tf(v.z); v.w = ftrunc_tf(v.w);
    *(float4*)&g_wtf[i] = v;
}

// ---------------- tf32 tensor-core GEMM, BM=64, 3-stage cp.async, LDSM ----
// MINB: min blocks/SM (3 for plain variants -> 24 warps/SM; 2 for gather/reshape)
__device__ __forceinline__ void mma_tf32(float c[4], const uint32_t a[4],
                                         uint32_t b0, uint32_t b1) {
    asm volatile(
        "mma.sync.aligned.m16n8k8.row.col.f32.tf32.tf32.f32 "
        "{%0,%1,%2,%3}, {%4,%5,%6,%7}, {%8,%9}, {%0,%1,%2,%3};"
        : "+f"(c[0]), "+f"(c[1]), "+f"(c[2]), "+f"(c[3])
        : "r"(a[0]), "r"(a[1]), "r"(a[2]), "r"(a[3]), "r"(b0), "r"(b1));
}
__device__ __forceinline__ float gelu_exact(float v) {
    return 0.5f * v * (1.0f + erff(v * 0.70710678118654752440f));
}
__device__ __forceinline__ void cp16(uint32_t saddr, const float* g, bool pred) {
    asm volatile("cp.async.cg.shared.global [%0], [%1], 16, %2;"
                 :: "r"(saddr), "l"(g), "r"(pred ? 16 : 0));
}
__device__ __forceinline__ void cp4(uint32_t saddr, const float* g, bool pred) {
    asm volatile("cp.async.ca.shared.global [%0], [%1], 4, %2;"
                 :: "r"(saddr), "l"(g), "r"(pred ? 4 : 0));
}
__device__ __forceinline__ void cp_commit() { asm volatile("cp.async.commit_group;"); }
template<int N>
__device__ __forceinline__ void cp_wait() {
    asm volatile("cp.async.wait_group %0;" :: "n"(N));
}
__device__ __forceinline__ int swz(int row, int col) {
    return row * 32 + (col ^ ((row & 7) * 4));
}
__device__ __forceinline__ void ldsm4(uint32_t addr, uint32_t& r0, uint32_t& r1,
                                      uint32_t& r2, uint32_t& r3) {
    asm volatile("ldmatrix.sync.aligned.m8n8.x4.shared.b16 {%0,%1,%2,%3}, [%4];"
                 : "=r"(r0), "=r"(r1), "=r"(r2), "=r"(r3) : "r"(addr));
}

#define GEMM_SMEM (3 * (64 * 32 + 4096) * 4)   // 73728 B

template<int MINB, int ACT, bool HASBIAS, bool HASRES, bool POSMOD, bool TRUNC,
         bool GATHER, bool RESHAPE>
__global__ void __launch_bounds__(256, MINB)
gemm_tc(const float* __restrict__ A, const float* __restrict__ W,
        const float* __restrict__ bias, const float* __restrict__ res,
        float* __restrict__ C, int M, int Nn, int K) {
    constexpr int BM = 64;
    constexpr int NWM = 2;
    constexpr int WN  = 32;
    constexpr int NP  = 2;
    constexpr int NT  = 4;
    constexpr int ASTG = BM * 32;

    extern __shared__ float smem[];
    float* As = smem;
    float* Ws = smem + 3 * ASTG;
    const int tid  = threadIdx.x;
    const int wid  = tid >> 5, lane = tid & 31;
    const int wm   = wid % NWM, wn = wid / NWM;
    const int gid  = lane >> 2, tig = lane & 3;
    const int m0   = blockIdx.y * BM, n0 = blockIdx.x * 128;

    const int lrow = tid >> 3;
    const int lc4  = (tid & 7) * 4;

    uint32_t As_base = (uint32_t)__cvta_generic_to_shared(As);
    uint32_t Ws_base = (uint32_t)__cvta_generic_to_shared(Ws);

    const int rowA_in  = (lane & 15);
    const int koffA    = ((lane >> 4) & 1) * 4;
    const int rowB_in  = (lane & 7) + (((lane >> 4) & 1) << 3);
    const int koffB    = ((lane >> 3) & 1) * 4;

    // per-row gather precompute (token -> batch / patch coords)
    bool grow[2];
    int  gb[2], gpy[2], gpx[2];
    if (GATHER) {
        #pragma unroll
        for (int i = 0; i < 2; i++) {
            int m = m0 + lrow + i * 32;
            grow[i] = m < M;
            int mm = m < M ? m : (M - 1);
            gb[i] = mm / NTOK;
            int n8 = mm - gb[i] * NTOK;
            gpy[i] = n8 / HP;
            gpx[i] = n8 - gpy[i] * HP;
        }
    }

    float acc[2][NT][4] = {};
    const int ktiles = K >> 5;

    auto load_tile = [&](int kt, int buf) {
        if (GATHER) {
            int c  = kt * 32 + lc4;
            int s  = c >> 8;
            int pr = (c >> 4) & 15;
            int pc = c & 15;
            int dy = (s == 0) ? 0 : ((s <= 2) ? -8 : 8);
            int dx = (s == 0) ? 0 : ((s & 1) ? -8 : 8);
            #pragma unroll
            for (int i = 0; i < 2; i++) {
                int row = lrow + i * 32;
                uint32_t sdst = As_base + (buf * ASTG + swz(row, lc4)) * 4;
                int y  = gpy[i] * 16 + pr - dy;
                if (y < 0) y += HPAD; if (y >= HPAD) y -= HPAD;
                int xx = gpx[i] * 16 + pc - dx;
                if (xx < 0) xx += HPAD; if (xx >= HPAD) xx -= HPAD;
                bool yv = grow[i] && (y < IMGS);
                const float* src = A + ((size_t)gb[i] * IMGS + y) * IMGS + xx;
                #pragma unroll
                for (int q = 0; q < 4; q++)
                    cp4(sdst + q * 4, src + q, yv && (xx + q) < IMGS);
            }
        } else {
            const float* Ag = A + (size_t)m0 * K + kt * 32;
            #pragma unroll
            for (int i = 0; i < 2; i++) {
                int row = lrow + i * 32;
                uint32_t s = As_base + (buf * ASTG + swz(row, lc4)) * 4;
                cp16(s, Ag + (size_t)row * K + lc4, (m0 + row) < M);
            }
        }
        const float* Wg = W + (size_t)n0 * K + kt * 32;
        #pragma unroll
        for (int i = 0; i < 4; i++) {
            int row = lrow + i * 32;
            uint32_t s = Ws_base + (buf * 4096 + swz(row, lc4)) * 4;
            cp16(s, Wg + (size_t)row * K + lc4, true);
        }
    };

    load_tile(0, 0);
    cp_commit();
    if (ktiles > 1) { load_tile(1, 1); cp_commit(); }

    for (int kt = 0; kt < ktiles; kt++) {
        if (kt + 2 < ktiles) {
            load_tile(kt + 2, (kt + 2) % 3);
            cp_commit();
            cp_wait<2>();
        } else if (kt + 1 < ktiles) {
            cp_wait<1>();
        } else {
            cp_wait<0>();
        }
        __syncthreads();

        const uint32_t as_b = As_base + ((kt % 3) * ASTG) * 4;
        const uint32_t ws_b = Ws_base + ((kt % 3) * 4096) * 4;
        #pragma unroll
        for (int ks = 0; ks < 32; ks += 8) {
            uint32_t af[2][4];
            #pragma unroll
            for (int mt = 0; mt < 2; mt++) {
                int row = wm * 32 + mt * 16 + rowA_in;
                int col = ks + koffA;
                uint32_t addr = as_b + (uint32_t)swz(row, col) * 4;
                ldsm4(addr, af[mt][0], af[mt][1], af[mt][2], af[mt][3]);
            }
            #pragma unroll
            for (int np = 0; np < NP; np++) {
                int row = wn * WN + np * 16 + rowB_in;
                int col = ks + koffB;
                uint32_t addr = ws_b + (uint32_t)swz(row, col) * 4;
                uint32_t b0a, b1a, b0b, b1b;
                ldsm4(addr, b0a, b1a, b0b, b1b);
                mma_tf32(acc[0][2 * np    ], af[0], b0a, b1a);
                mma_tf32(acc[1][2 * np    ], af[1], b0a, b1a);
                mma_tf32(acc[0][2 * np + 1], af[0], b0b, b1b);
                mma_tf32(acc[1][2 * np + 1], af[1], b0b, b1b);
            }
        }
        __syncthreads();
    }

    #pragma unroll
    for (int mt = 0; mt < 2; mt++) {
        #pragma unroll
        for (int half = 0; half < 2; half++) {
            int m = m0 + wm * 32 + mt * 16 + gid + half * 8;
            if (m >= M) continue;
            int mres = POSMOD ? (m % NTOK) : m;
            int ob = 0, opy = 0, opx = 0;
            if (RESHAPE) {
                ob = m / NTOK;
                int n8 = m - ob * NTOK;
                opy = n8 / HP;
                opx = n8 - opy * HP;
            }
            #pragma unroll
            for (int nt = 0; nt < NT; nt++) {
                int n = n0 + wn * WN + nt * 8 + tig * 2;
                float v0 = acc[mt][nt][half * 2 + 0];
                float v1 = acc[mt][nt][half * 2 + 1];
                if (HASBIAS) { v0 += bias[n]; v1 += bias[n + 1]; }
                if (ACT == 1) { v0 = gelu_exact(v0); v1 = gelu_exact(v1); }
                if (HASRES) {
                    float2 r = *(const float2*)&res[(size_t)mres * Nn + n];
                    v0 += r.x; v1 += r.y;
                }
                if (TRUNC) { v0 = ftrunc_tf(v0); v1 = ftrunc_tf(v1); }
                if (RESHAPE) {
                    int y  = opy * 16 + (n >> 4);
                    int xc = opx * 16 + (n & 15);
                    if (y < IMGS) {
                        float* orow = C + ((size_t)ob * IMGS + y) * IMGS;
                        if (xc < IMGS)     orow[xc]     = v0;
                        if (xc + 1 < IMGS) orow[xc + 1] = v1;
                    }
                } else {
                    *(float2*)&C[(size_t)m * Nn + n] = make_float2(v0, v1);
                }
            }
        }
    }
}

// ---------------- LayerNorm (warp/token, float4, tf32-truncated out) ------
__global__ void ln_kernel(const float* __restrict__ in, const float* __restrict__ w,
                          const float* __restrict__ b, float* __restrict__ out) {
    int warp = threadIdx.x / 32, lane = threadIdx.x % 32;
    int m = blockIdx.x * 8 + warp;
    if (m >= MTOK) return;
    const float* row = in + (size_t)m * DIM + lane * 8;
    float4 a = *(const float4*)row;
    float4 c = *(const float4*)(row + 4);
    float s  = a.x + a.y + a.z + a.w + c.x + c.y + c.z + c.w;
    float s2 = a.x*a.x + a.y*a.y + a.z*a.z + a.w*a.w
             + c.x*c.x + c.y*c.y + c.z*c.z + c.w*c.w;
    #pragma unroll
    for (int o = 16; o; o >>= 1) {
        s  += __shfl_xor_sync(0xffffffffu, s,  o);
        s2 += __shfl_xor_sync(0xffffffffu, s2, o);
    }
    float mean = s * (1.f / 256.f);
    float var  = s2 * (1.f / 256.f) - mean * mean;
    float rstd = rsqrtf(var + 1e-5f);
    float4 w0 = *(const float4*)(w + lane * 8);
    float4 w1 = *(const float4*)(w + lane * 8 + 4);
    float4 b0 = *(const float4*)(b + lane * 8);
    float4 b1 = *(const float4*)(b + lane * 8 + 4);
    float4 o0, o1;
    o0.x = ftrunc_tf((a.x - mean) * rstd * w0.x + b0.x);
    o0.y = ftrunc_tf((a.y - mean) * rstd * w0.y + b0.y);
    o0.z = ftrunc_tf((a.z - mean) * rstd * w0.z + b0.z);
    o0.w = ftrunc_tf((a.w - mean) * rstd * w0.w + b0.w);
    o1.x = ftrunc_tf((c.x - mean) * rstd * w1.x + b1.x);
    o1.y = ftrunc_tf((c.y - mean) * rstd * w1.y + b1.y);
    o1.z = ftrunc_tf((c.z - mean) * rstd * w1.z + b1.z);
    o1.w = ftrunc_tf((c.w - mean) * rstd * w1.w + b1.w);
    float* orow = out + (size_t)m * DIM + lane * 8;
    *(float4*)orow = o0;
    *(float4*)(orow + 4) = o1;
}

// ---------------- MMA flash attention, q-tile 128, 8 warps ----------------
__global__ void __launch_bounds__(256)
attn_mma(const float* __restrict__ scale_d) {
    __shared__ uint32_t Ks[32 * 36];
    __shared__ uint32_t Vs[32 * 40];
    __shared__ uint32_t Ps[8][16 * 36];

    const int bh = blockIdx.y;
    const int b = bh >> 3, h = bh & 7;
    const int tid = threadIdx.x;
    const int warp = tid >> 5, lane = tid & 31;
    const int gid = lane >> 2, tig = lane & 3;
    const int q0 = (gridDim.x - 1 - blockIdx.x) * 128;  // longest blocks first
    const float* base = g_qkv + (size_t)b * NTOK * 768;
    const float sc = scale_d[h];

    const int i0 = q0 + warp * 16 + gid;
    const int i1 = i0 + 8;

    uint32_t qf[4][4];
    #pragma unroll
    for (int ks = 0; ks < 4; ks++) {
        int c = h * 32 + ks * 8 + tig;
        float v00 = 0.f, v10 = 0.f, v01 = 0.f, v11 = 0.f;
        if (i0 < NTOK) { v00 = base[(size_t)i0 * 768 + c] * sc;
                         v01 = base[(size_t)i0 * 768 + c + 4] * sc; }
        if (i1 < NTOK) { v10 = base[(size_t)i1 * 768 + c] * sc;
                         v11 = base[(size_t)i1 * 768 + c + 4] * sc; }
        qf[ks][0] = f2tf(v00); qf[ks][1] = f2tf(v10);
        qf[ks][2] = f2tf(v01); qf[ks][3] = f2tf(v11);
    }

    float m0 = -1e30f, m1 = -1e30f, l0 = 0.f, l1 = 0.f;
    float oacc[4][4] = {};

    const int jmax = min(q0 + 127, NTOK - 1);
    for (int j0 = 0; j0 < jmax; j0 += 32) {
        __syncthreads();
        {
            int r  = tid >> 3;
            int c4 = (tid & 7) * 4;
            int j  = j0 + r;
            if (j < NTOK) {
                const float* kp = base + (size_t)j * 768 + 256 + h * 32 + c4;
                const float* vp = base + (size_t)j * 768 + 512 + h * 32 + c4;
                float4 ka = *(const float4*)kp;
                Ks[r * 36 + c4 + 0] = f2tf(ka.x); Ks[r * 36 + c4 + 1] = f2tf(ka.y);
                Ks[r * 36 + c4 + 2] = f2tf(ka.z); Ks[r * 36 + c4 + 3] = f2tf(ka.w);
                float4 va = *(const float4*)vp;
                Vs[r * 40 + c4 + 0] = f2tf(va.x); Vs[r * 40 + c4 + 1] = f2tf(va.y);
                Vs[r * 40 + c4 + 2] = f2tf(va.z); Vs[r * 40 + c4 + 3] = f2tf(va.w);
            } else {
                #pragma unroll
                for (int q = 0; q < 4; q++) {
                    Ks[r * 36 + c4 + q] = 0;
                    Vs[r * 40 + c4 + q] = 0;
                }
            }
        }
        __syncthreads();

        float s[4][4] = {};
        #pragma unroll
        for (int ks = 0; ks < 4; ks++) {
            #pragma unroll
            for (int nt = 0; nt < 4; nt++) {
                uint32_t b0 = Ks[(nt * 8 + gid) * 36 + ks * 8 + tig];
                uint32_t b1 = Ks[(nt * 8 + gid) * 36 + ks * 8 + tig + 4];
                mma_tf32(s[nt], qf[ks], b0, b1);
            }
        }

        float rm0 = -1e30f, rm1 = -1e30f;
        #pragma unroll
        for (int nt = 0; nt < 4; nt++) {
            int jc = j0 + nt * 8 + tig * 2;
            if (jc     >= i0) s[nt][0] = -1e30f;
            if (jc + 1 >= i0) s[nt][1] = -1e30f;
            if (jc     >= i1) s[nt][2] = -1e30f;
            if (jc + 1 >= i1) s[nt][3] = -1e30f;
            rm0 = fmaxf(rm0, fmaxf(s[nt][0], s[nt][1]));
            rm1 = fmaxf(rm1, fmaxf(s[nt][2], s[nt][3]));
        }
        rm0 = fmaxf(rm0, __shfl_xor_sync(0xffffffffu, rm0, 1));
        rm0 = fmaxf(rm0, __shfl_xor_sync(0xffffffffu, rm0, 2));
        rm1 = fmaxf(rm1, __shfl_xor_sync(0xffffffffu, rm1, 1));
        rm1 = fmaxf(rm1, __shfl_xor_sync(0xffffffffu, rm1, 2));
        float mn0 = fmaxf(m0, rm0), mn1 = fmaxf(m1, rm1);
        float corr0 = __expf(m0 - mn0), corr1 = __expf(m1 - mn1);

        float p[4][4];
        float ps0 = 0.f, ps1 = 0.f;
        #pragma unroll
        for (int nt = 0; nt < 4; nt++) {
            p[nt][0] = (s[nt][0] < -1e29f) ? 0.f : __expf(s[nt][0] - mn0);
            p[nt][1] = (s[nt][1] < -1e29f) ? 0.f : __expf(s[nt][1] - mn0);
            p[nt][2] = (s[nt][2] < -1e29f) ? 0.f : __expf(s[nt][2] - mn1);
            p[nt][3] = (s[nt][3] < -1e29f) ? 0.f : __expf(s[nt][3] - mn1);
            ps0 += p[nt][0] + p[nt][1];
            ps1 += p[nt][2] + p[nt][3];
        }
        ps0 += __shfl_xor_sync(0xffffffffu, ps0, 1);
        ps0 += __shfl_xor_sync(0xffffffffu, ps0, 2);
        ps1 += __shfl_xor_sync(0xffffffffu, ps1, 1);
        ps1 += __shfl_xor_sync(0xffffffffu, ps1, 2);
        l0 = l0 * corr0 + ps0;
        l1 = l1 * corr1 + ps1;
        #pragma unroll
        for (int nt = 0; nt < 4; nt++) {
            oacc[nt][0] *= corr0; oacc[nt][1] *= corr0;
            oacc[nt][2] *= corr1; oacc[nt][3] *= corr1;
        }

        uint32_t* pw = Ps[warp];
        __syncwarp();
        #pragma unroll
        for (int nt = 0; nt < 4; nt++) {
            pw[gid * 36 + nt * 8 + tig * 2    ]  = f2tf(p[nt][0]);
            pw[gid * 36 + nt * 8 + tig * 2 + 1]  = f2tf(p[nt][1]);
            pw[(gid + 8) * 36 + nt * 8 + tig * 2    ] = f2tf(p[nt][2]);
            pw[(gid + 8) * 36 + nt * 8 + tig * 2 + 1] = f2tf(p[nt][3]);
        }
        __syncwarp();

        #pragma unroll
        for (int ks = 0; ks < 4; ks++) {
            uint32_t af[4];
            af[0] = pw[gid * 36 + ks * 8 + tig];
            af[1] = pw[(gid + 8) * 36 + ks * 8 + tig];
            af[2] = pw[gid * 36 + ks * 8 + tig + 4];
            af[3] = pw[(gid + 8) * 36 + ks * 8 + tig + 4];
            #pragma unroll
            for (int nt = 0; nt < 4; nt++) {
                uint32_t b0 = Vs[(ks * 8 + tig) * 40 + nt * 8 + gid];
                uint32_t b1 = Vs[(ks * 8 + tig + 4) * 40 + nt * 8 + gid];
                mma_tf32(oacc[nt], af, b0, b1);
            }
        }
        m0 = mn0; m1 = mn1;
    }

    float inv0 = (l0 > 0.f) ? 1.f / l0 : 0.f;
    float inv1 = (l1 > 0.f) ? 1.f / l1 : 0.f;
    #pragma unroll
    for (int nt = 0; nt < 4; nt++) {
        int col = h * 32 + nt * 8 + tig * 2;
        if (i0 < NTOK) {
            float2 o = make_float2(ftrunc_tf(oacc[nt][0] * inv0),
                                   ftrunc_tf(oacc[nt][1] * inv0));
            *(float2*)&g_attn[((size_t)b * NTOK + i0) * DIM + col] = o;
        }
        if (i1 < NTOK) {
            float2 o = make_float2(ftrunc_tf(oacc[nt][2] * inv1),
                                   ftrunc_tf(oacc[nt][3] * inv1));
            *(float2*)&g_attn[((size_t)b * NTOK + i1) * DIM + col] = o;
        }
    }
}

// ---------------- host orchestration ---------------------------------------
static inline dim3 gg(int M, int Nn) { return dim3(Nn / 128, (M + 63) / 64); }

extern "C" void kernel_launch(void* const* d_in, const int* in_sizes, int n_in,
                              void* d_out, int out_size) {
    const float* x      = (const float*)d_in[0];
    const float* pos    = (const float*)d_in[1];
    const float* spt_w  = (const float*)d_in[2];
    const float* spt_b  = (const float*)d_in[3];
    const float* ln1_w  = (const float*)d_in[4];
    const float* ln1_b  = (const float*)d_in[5];
    const float* scale  = (const float*)d_in[6];
    const float* wqkv   = (const float*)d_in[7];
    const float* wout   = (const float*)d_in[8];
    const float* bout   = (const float*)d_in[9];
    const float* ln2_w  = (const float*)d_in[10];
    const float* ln2_b  = (const float*)d_in[11];
    const float* ff1_w  = (const float*)d_in[12];
    const float* ff1_b  = (const float*)d_in[13];
    const float* ff2_w  = (const float*)d_in[14];
    const float* ff2_b  = (const float*)d_in[15];
    const float* pix_w  = (const float*)d_in[16];
    const float* pix_b  = (const float*)d_in[17];

    float *t, *ln, *qkv, *attn, *ff, *wtf;
    cudaGetSymbolAddress((void**)&t,    g_t);
    cudaGetSymbolAddress((void**)&ln,   g_ln);
    cudaGetSymbolAddress((void**)&qkv,  g_qkv);
    cudaGetSymbolAddress((void**)&attn, g_attn);
    cudaGetSymbolAddress((void**)&ff,   g_ff);
    cudaGetSymbolAddress((void**)&wtf,  g_wtf);

    // gather (spt) / reshape (pix): minB=2 ; plain GEMMs: minB=3
    cudaFuncSetAttribute(gemm_tc<2, 0, true,  true,  true,  false, true,  false>, cudaFuncAttributeMaxDynamicSharedMemorySize, GEMM_SMEM);
    cudaFuncSetAttribute(gemm_tc<2, 0, true,  false, false, false, false, true >, cudaFuncAttributeMaxDynamicSharedMemorySize, GEMM_SMEM);
    cudaFuncSetAttribute(gemm_tc<3, 0, false, false, false, false, false, false>, cudaFuncAttributeMaxDynamicSharedMemorySize, GEMM_SMEM);
    cudaFuncSetAttribute(gemm_tc<3, 0, true,  true,  false, false, false, false>, cudaFuncAttributeMaxDynamicSharedMemorySize, GEMM_SMEM);
    cudaFuncSetAttribute(gemm_tc<3, 1, true,  false, false, true,  false, false>, cudaFuncAttributeMaxDynamicSharedMemorySize, GEMM_SMEM);

    convert_w<<<(W_TOTAL / 4 + 255) / 256, 256>>>(spt_w, wqkv, wout, ff1_w, ff2_w, pix_w);

    // spt projection with fused tokenize gather + pos residual
    gemm_tc<2, 0, true, true, true, false, true, false><<<gg(MTOK, DIM), 256, GEMM_SMEM>>>(
        x, wtf + W_SPT_OFF, spt_b, pos, t, MTOK, DIM, 1280);

    const int LN_BLOCKS = (MTOK + 7) / 8;
    for (int d = 0; d < 3; d++) {
        ln_kernel<<<LN_BLOCKS, 256>>>(t, ln1_w + d * DIM, ln1_b + d * DIM, ln);
        gemm_tc<3, 0, false, false, false, false, false, false><<<gg(MTOK, 768), 256, GEMM_SMEM>>>(
            ln, wtf + W_QKV_OFF + (size_t)d * 768 * DIM, nullptr, nullptr, qkv, MTOK, 768, DIM);
        {
            dim3 grid((NTOK + 127) / 128, BATCH * NHEADS);
            attn_mma<<<grid, 256>>>(scale + d * NHEADS);
        }
        gemm_tc<3, 0, true, true, false, false, false, false><<<gg(MTOK, DIM), 256, GEMM_SMEM>>>(
            attn, wtf + W_WOUT_OFF + (size_t)d * DIM * DIM, bout + d * DIM, t, t, MTOK, DIM, DIM);
        ln_kernel<<<LN_BLOCKS, 256>>>(t, ln2_w + d * DIM, ln2_b + d * DIM, ln);
        gemm_tc<3, 1, true, false, false, true, false, false><<<gg(MTOK, 1024), 256, GEMM_SMEM>>>(
            ln, wtf + W_FF1_OFF + (size_t)d * 1024 * DIM, ff1_b + d * 1024, nullptr, ff, MTOK, 1024, DIM);
        gemm_tc<3, 0, true, true, false, false, false, false><<<gg(MTOK, DIM), 256, GEMM_SMEM>>>(
            ff, wtf + W_FF2_OFF + (size_t)d * DIM * 1024, ff2_b + d * DIM, t, t, MTOK, DIM, 1024);
    }

    // pix projection with fused untokenize + crop (writes d_out directly)
    gemm_tc<2, 0, true, false, false, false, false, true><<<gg(MTOK, DIM), 256, GEMM_SMEM>>>(
        t, wtf + W_PIX_OFF, pix_b, nullptr, (float*)d_out, MTOK, DIM, DIM);
}